// round 6
// baseline (speedup 1.0000x reference)
#include <cuda_runtime.h>
#include <math.h>
#include <stdint.h>

// ---- problem dims ----
#define DM   512
#define DI   1024
#define DS   64
#define DTR  32
#define NB   2
#define LSEQ 1024
#define NTOK (NB*LSEQ)
#define XDBW (DTR + 2*DS)   // 160
#define SPLITK_WX 8

// ---- scratch ----
__device__ float g_xn[NTOK*DM];
__device__ float g_xz[(size_t)NTOK*2*DI];
__device__ float g_x[(size_t)NTOK*DI];
__device__ float g_xdb[(size_t)NTOK*XDBW];
__device__ float g_xdb_part[(size_t)SPLITK_WX*NTOK*XDBW];
__device__ float g_delta[(size_t)NTOK*DI];
__device__ float g_yv[(size_t)NTOK*DI];

// =====================================================================
// helpers
// =====================================================================
__device__ __forceinline__ void cp_async16(uint32_t saddr, const void* gaddr) {
    asm volatile("cp.async.cg.shared.global [%0], [%1], 16;\n" :: "r"(saddr), "l"(gaddr));
}
#define CP_COMMIT() asm volatile("cp.async.commit_group;\n" ::: "memory")
#define CP_WAIT0()  asm volatile("cp.async.wait_group 0;\n" ::: "memory")

// =====================================================================
// LayerNorm
// =====================================================================
__global__ void ln_kernel(const float* __restrict__ frames,
                          const float* __restrict__ gamma,
                          const float* __restrict__ beta,
                          float* __restrict__ xn) {
    int m = blockIdx.x;
    int tid = threadIdx.x;
    const float4* r = (const float4*)(frames + (size_t)m * DM);
    float4 v = r[tid];
    float s  = v.x + v.y + v.z + v.w;
    float sq = v.x*v.x + v.y*v.y + v.z*v.z + v.w*v.w;
    #pragma unroll
    for (int o = 16; o; o >>= 1) {
        s  += __shfl_xor_sync(~0u, s,  o);
        sq += __shfl_xor_sync(~0u, sq, o);
    }
    __shared__ float ss[4], ssq[4];
    int w = tid >> 5, lane = tid & 31;
    if (lane == 0) { ss[w] = s; ssq[w] = sq; }
    __syncthreads();
    s  = ss[0] + ss[1] + ss[2] + ss[3];
    sq = ssq[0] + ssq[1] + ssq[2] + ssq[3];
    float mean = s * (1.f / DM);
    float var  = sq * (1.f / DM) - mean * mean;
    float rstd = rsqrtf(var + 1e-5f);
    float4 g  = ((const float4*)gamma)[tid];
    float4 bt = ((const float4*)beta)[tid];
    float4 o;
    o.x = (v.x - mean) * rstd * g.x + bt.x;
    o.y = (v.y - mean) * rstd * g.y + bt.y;
    o.z = (v.z - mean) * rstd * g.z + bt.z;
    o.w = (v.w - mean) * rstd * g.w + bt.w;
    ((float4*)(xn + (size_t)m * DM))[tid] = o;
}

// =====================================================================
// TF32 tensor-core GEMM, cp.async double-buffered, BK=32.
// =====================================================================
#define EPI_NONE     0
#define EPI_SOFTPLUS 1
#define EPI_RESID    2
#define EPI_PART     3

__device__ __forceinline__ void mma_tf32(float c[4], const uint32_t a[4], const uint32_t b[2]) {
    asm volatile(
        "mma.sync.aligned.m16n8k8.row.col.f32.tf32.tf32.f32 "
        "{%0,%1,%2,%3}, {%4,%5,%6,%7}, {%8,%9}, {%0,%1,%2,%3};"
        : "+f"(c[0]), "+f"(c[1]), "+f"(c[2]), "+f"(c[3])
        : "r"(a[0]), "r"(a[1]), "r"(a[2]), "r"(a[3]), "r"(b[0]), "r"(b[1]));
}

template<int BM, int BN, int EPI, int SPLITK>
__global__ void tgemm_kernel(const float* __restrict__ A,
                             const float* __restrict__ B,
                             float* __restrict__ C,
                             int M, int N, int K,
                             int lda, int ldb, int ldc,
                             const float* __restrict__ aux) {
    constexpr int BK = 32;
    constexpr int WM = BM / 32, WN = BN / 32;
    constexpr int THREADS = WM * WN * 32;
    constexpr int AST = BK + 4;
    constexpr int BST = BN + 8;
    constexpr int ABUF = BM * AST;
    constexpr int BBUF = BK * BST;

    extern __shared__ float sm[];
    float* Asm = sm;
    float* Bsm = sm + 2 * ABUF;
    uint32_t sa = (uint32_t)__cvta_generic_to_shared(Asm);
    uint32_t sb = (uint32_t)__cvta_generic_to_shared(Bsm);

    int tid = threadIdx.x, lane = tid & 31, wid = tid >> 5;
    int wm = wid % WM, wn = wid / WM;
    int m0 = blockIdx.y * BM, n0 = blockIdx.x * BN;
    int wrow = wm * 32, wcol = wn * 32;
    int g = lane >> 2, tg = lane & 3;

    int kbase = (SPLITK > 1) ? blockIdx.z * (K / SPLITK) : 0;
    int kcnt  = (K / SPLITK) / BK;

    float acc[2][4][4];
    #pragma unroll
    for (int a = 0; a < 2; a++)
        #pragma unroll
        for (int b = 0; b < 4; b++)
            #pragma unroll
            for (int c = 0; c < 4; c++) acc[a][b][c] = 0.f;

    auto loadA = [&](int kt, int buf) {
        const float* Ap = A + (size_t)m0 * lda + kbase + kt * BK;
        #pragma unroll
        for (int i = tid; i < BM * (BK / 4); i += THREADS) {
            int r = i / (BK / 4), c = (i % (BK / 4)) * 4;
            cp_async16(sa + (uint32_t)(buf * ABUF + r * AST + c) * 4,
                       Ap + (size_t)r * lda + c);
        }
    };
    auto loadB = [&](int kt, int buf) {
        const float* Bp = B + (size_t)(kbase + kt * BK) * ldb + n0;
        #pragma unroll
        for (int i = tid; i < BK * (BN / 4); i += THREADS) {
            int r = i / (BN / 4), c = (i % (BN / 4)) * 4;
            cp_async16(sb + (uint32_t)(buf * BBUF + r * BST + c) * 4,
                       Bp + (size_t)r * ldb + c);
        }
    };

    loadA(0, 0); loadB(0, 0); CP_COMMIT();

    for (int kt = 0; kt < kcnt; kt++) {
        CP_WAIT0();
        __syncthreads();
        if (kt + 1 < kcnt) {
            int nb = (kt + 1) & 1;
            loadA(kt + 1, nb); loadB(kt + 1, nb); CP_COMMIT();
        }
        int cb = kt & 1;
        const float* Ab = Asm + cb * ABUF;
        const float* Bb = Bsm + cb * BBUF;
        #pragma unroll
        for (int ks = 0; ks < 4; ks++) {
            int kb = ks * 8;
            uint32_t af[2][4], bf[4][2];
            #pragma unroll
            for (int mt = 0; mt < 2; mt++) {
                int r = wrow + mt * 16;
                af[mt][0] = __float_as_uint(Ab[(r + g)     * AST + kb + tg]);
                af[mt][1] = __float_as_uint(Ab[(r + 8 + g) * AST + kb + tg]);
                af[mt][2] = __float_as_uint(Ab[(r + g)     * AST + kb + 4 + tg]);
                af[mt][3] = __float_as_uint(Ab[(r + 8 + g) * AST + kb + 4 + tg]);
            }
            #pragma unroll
            for (int nt = 0; nt < 4; nt++) {
                int c = wcol + nt * 8 + g;
                bf[nt][0] = __float_as_uint(Bb[(kb + tg)     * BST + c]);
                bf[nt][1] = __float_as_uint(Bb[(kb + 4 + tg) * BST + c]);
            }
            #pragma unroll
            for (int mt = 0; mt < 2; mt++)
                #pragma unroll
                for (int nt = 0; nt < 4; nt++)
                    mma_tf32(acc[mt][nt], af[mt], bf[nt]);
        }
        __syncthreads();
    }

    float* Cw = C;
    if (EPI == EPI_PART) Cw = C + (size_t)blockIdx.z * M * ldc;

    #pragma unroll
    for (int mt = 0; mt < 2; mt++) {
        #pragma unroll
        for (int nt = 0; nt < 4; nt++) {
            int row0 = m0 + wrow + mt * 16 + g;
            int col  = n0 + wcol + nt * 8 + tg * 2;
            #pragma unroll
            for (int h = 0; h < 2; h++) {
                size_t row = row0 + h * 8;
                float v0 = acc[mt][nt][h * 2 + 0];
                float v1 = acc[mt][nt][h * 2 + 1];
                if (EPI == EPI_SOFTPLUS) {
                    v0 += aux[col];     v1 += aux[col + 1];
                    v0 = fmaxf(v0, 0.f) + log1pf(__expf(-fabsf(v0)));
                    v1 = fmaxf(v1, 0.f) + log1pf(__expf(-fabsf(v1)));
                }
                if (EPI == EPI_RESID) {
                    v0 += aux[row * ldc + col];
                    v1 += aux[row * ldc + col + 1];
                }
                *(float2*)(Cw + row * ldc + col) = make_float2(v0, v1);
            }
        }
    }
}

// =====================================================================
// reduce SPLITK_WX split-K partials
// =====================================================================
__global__ void reduce8_kernel(const float4* __restrict__ part,
                               float4* __restrict__ out, int n4) {
    int i = blockIdx.x * blockDim.x + threadIdx.x;
    if (i >= n4) return;
    float4 o = part[i];
    #pragma unroll
    for (int p = 1; p < SPLITK_WX; p++) {
        float4 a = part[i + (size_t)p * n4];
        o.x += a.x; o.y += a.y; o.z += a.z; o.w += a.w;
    }
    out[i] = o;
}

// =====================================================================
// Causal depthwise conv + bias + SiLU
// =====================================================================
__global__ void conv_silu_kernel(const float* __restrict__ xz,
                                 const float* __restrict__ cw,
                                 const float* __restrict__ cb,
                                 float* __restrict__ xo) {
    int idx = blockIdx.x * blockDim.x + threadIdx.x;
    if (idx >= NTOK * DI) return;
    int d = idx & (DI - 1);
    int token = idx >> 10;
    int t = token & (LSEQ - 1);
    float4 w = ((const float4*)cw)[d];
    const float* p = xz + (size_t)token * (2 * DI) + d;
    float acc = cb[d];
    if (t >= 3) acc += w.x * p[-3 * 2 * DI];
    if (t >= 2) acc += w.y * p[-2 * 2 * DI];
    if (t >= 1) acc += w.z * p[-1 * 2 * DI];
    acc += w.w * p[0];
    xo[idx] = acc / (1.f + __expf(-acc));
}

// =====================================================================
// Selective scan + fused gated epilogue.
// Each warp owns TWO adjacent channels (B/C tiles shared); lane holds
// states 2l,2l+1 of each. Two independent shfl butterflies interleave,
// hiding shuffle latency. Output pair written as one STG.64.
// =====================================================================
#define SCAN_WARPS 4
#define CPB (2*SCAN_WARPS)   // channels per block = 8
#define TCH 64

__global__ void scan_kernel(const float* __restrict__ delta,
                            const float* __restrict__ xconv,
                            const float* __restrict__ xdb,
                            const float* __restrict__ xz,
                            const float* __restrict__ A_log,
                            const float* __restrict__ Dv,
                            float* __restrict__ yv) {
    int b  = blockIdx.y;
    int d0 = blockIdx.x * CPB;
    int tid = threadIdx.x;               // 128
    int w = tid >> 5, lane = tid & 31;
    int dA = d0 + 2 * w;                 // first channel of this warp
    int dB = dA + 1;

    __shared__ float  Bs[TCH][DS];
    __shared__ float  Cs[TCH][DS];
    __shared__ float2 ds2[CPB][TCH];     // (delta, x) per channel
    __shared__ float  zs[CPB][TCH];

    float a0A = -__expf(A_log[(size_t)dA * DS + 2 * lane]);
    float a1A = -__expf(A_log[(size_t)dA * DS + 2 * lane + 1]);
    float a0B = -__expf(A_log[(size_t)dB * DS + 2 * lane]);
    float a1B = -__expf(A_log[(size_t)dB * DS + 2 * lane + 1]);
    float DvA = Dv[dA], DvB = Dv[dB];
    float h0A = 0.f, h1A = 0.f, h0B = 0.f, h1B = 0.f;

    for (int tc = 0; tc < LSEQ; tc += TCH) {
        __syncthreads();
        // stage B, C (shared across channels)
        for (int i = tid; i < TCH * (DS / 4); i += SCAN_WARPS * 32) {
            int t  = i >> 4;
            int s4 = (i & 15) << 2;
            const float* p = xdb + (size_t)(b * LSEQ + tc + t) * XDBW;
            *(float4*)&Bs[t][s4] = *(const float4*)(p + DTR + s4);
            *(float4*)&Cs[t][s4] = *(const float4*)(p + DTR + DS + s4);
        }
        // stage delta/x/z for the CPB channels
        for (int i = tid; i < CPB * TCH; i += SCAN_WARPS * 32) {
            int ch = i & (CPB - 1);
            int t  = i >> 3;
            size_t tok = (size_t)(b * LSEQ + tc + t);
            ds2[ch][t] = make_float2(delta[tok * DI + d0 + ch],
                                     xconv[tok * DI + d0 + ch]);
            zs[ch][t]  = xz[tok * (2 * DI) + DI + d0 + ch];
        }
        __syncthreads();

        #pragma unroll 4
        for (int i = 0; i < TCH; i++) {
            float2 da = ds2[2 * w][i];
            float2 db = ds2[2 * w + 1][i];
            float2 bv = *(float2*)&Bs[i][2 * lane];
            float2 cv = *(float2*)&Cs[i][2 * lane];
            float dxA = da.x * da.y;
            float dxB = db.x * db.y;
            h0A = fmaf(h0A, __expf(da.x * a0A), dxA * bv.x);
            h1A = fmaf(h1A, __expf(da.x * a1A), dxA * bv.y);
            h0B = fmaf(h0B, __expf(db.x * a0B), dxB * bv.x);
            h1B = fmaf(h1B, __expf(db.x * a1B), dxB * bv.y);
            float pA = fmaf(h0A, cv.x, h1A * cv.y);
            float pB = fmaf(h0B, cv.x, h1B * cv.y);
            #pragma unroll
            for (int o = 16; o; o >>= 1) {
                pA += __shfl_xor_sync(~0u, pA, o);
                pB += __shfl_xor_sync(~0u, pB, o);
            }
            if (lane == 0) {
                float zA = zs[2 * w][i], zB = zs[2 * w + 1][i];
                float szA = zA / (1.f + __expf(-zA));
                float szB = zB / (1.f + __expf(-zB));
                float2 o2 = make_float2(fmaf(da.y, DvA, pA) * szA,
                                        fmaf(db.y, DvB, pB) * szB);
                *(float2*)(yv + (size_t)(b * LSEQ + tc + i) * DI + dA) = o2;
            }
        }
    }
}

// =====================================================================
// launch
// =====================================================================
extern "C" void kernel_launch(void* const* d_in, const int* in_sizes, int n_in,
                              void* d_out, int out_size) {
    const float* frames = (const float*)d_in[0];
    const float* gamma  = (const float*)d_in[1];
    const float* beta   = (const float*)d_in[2];
    const float* W_in   = (const float*)d_in[3];
    const float* conv_w = (const float*)d_in[4];
    const float* conv_b = (const float*)d_in[5];
    const float* W_x    = (const float*)d_in[6];
    const float* W_dt   = (const float*)d_in[7];
    const float* b_dt   = (const float*)d_in[8];
    const float* A_log  = (const float*)d_in[9];
    const float* Dv     = (const float*)d_in[10];
    const float* W_out  = (const float*)d_in[11];
    float* out = (float*)d_out;

    float *xn, *xz, *x, *xdb, *xdbp, *delta, *yv;
    cudaGetSymbolAddress((void**)&xn,    g_xn);
    cudaGetSymbolAddress((void**)&xz,    g_xz);
    cudaGetSymbolAddress((void**)&x,     g_x);
    cudaGetSymbolAddress((void**)&xdb,   g_xdb);
    cudaGetSymbolAddress((void**)&xdbp,  g_xdb_part);
    cudaGetSymbolAddress((void**)&delta, g_delta);
    cudaGetSymbolAddress((void**)&yv,    g_yv);

    constexpr int SM_12864 = (2*128*36 + 2*32*72) * 4;  // 55296
    constexpr int SM_12832 = (2*128*36 + 2*32*40) * 4;  // 47104
    constexpr int SM_6464  = (2*64*36  + 2*32*72) * 4;  // 36864

    static bool attr_done = false;
    if (!attr_done) {
        cudaFuncSetAttribute((const void*)tgemm_kernel<128,64,EPI_NONE,1>,
                             cudaFuncAttributeMaxDynamicSharedMemorySize, SM_12864);
        cudaFuncSetAttribute((const void*)tgemm_kernel<128,32,EPI_PART,SPLITK_WX>,
                             cudaFuncAttributeMaxDynamicSharedMemorySize, SM_12832);
        cudaFuncSetAttribute((const void*)tgemm_kernel<64,64,EPI_SOFTPLUS,1>,
                             cudaFuncAttributeMaxDynamicSharedMemorySize, SM_6464);
        cudaFuncSetAttribute((const void*)tgemm_kernel<64,64,EPI_RESID,1>,
                             cudaFuncAttributeMaxDynamicSharedMemorySize, SM_6464);
        attr_done = true;
    }

    // 1. LayerNorm
    ln_kernel<<<NTOK, 128>>>(frames, gamma, beta, xn);

    // 2. in_proj: xz = xn @ W_in  (2048 x 2048 x 512)
    tgemm_kernel<128,64,EPI_NONE,1>
        <<<dim3(2*DI/64, NTOK/128), 256, SM_12864>>>(xn, W_in, xz,
            NTOK, 2*DI, DM, DM, 2*DI, 2*DI, nullptr);

    // 3. causal conv + silu
    conv_silu_kernel<<<(NTOK*DI)/256, 256>>>(xz, conv_w, conv_b, x);

    // 4. xdb = x @ W_x  (2048 x 160 x 1024), split-K=8
    tgemm_kernel<128,32,EPI_PART,SPLITK_WX>
        <<<dim3(XDBW/32, NTOK/128, SPLITK_WX), 128, SM_12832>>>(x, W_x, xdbp,
            NTOK, XDBW, DI, DI, XDBW, XDBW, nullptr);
    reduce8_kernel<<<(NTOK*XDBW/4 + 255)/256, 256>>>(
        (const float4*)xdbp, (float4*)xdb, NTOK*XDBW/4);

    // 5. delta = softplus(xdb[:, :32] @ W_dt + b_dt)
    tgemm_kernel<64,64,EPI_SOFTPLUS,1>
        <<<dim3(DI/64, NTOK/64), 128, SM_6464>>>(xdb, W_dt, delta,
            NTOK, DI, DTR, XDBW, DI, DI, b_dt);

    // 6. selective scan + fused gated epilogue (2 channels/warp)
    scan_kernel<<<dim3(DI/CPB, NB), SCAN_WARPS*32>>>(
        delta, x, xdb, xz, A_log, Dv, yv);

    // 7. out_proj + residual
    tgemm_kernel<64,64,EPI_RESID,1>
        <<<dim3(DM/64, NTOK/64), 128, SM_6464>>>(yv, W_out, out,
            NTOK, DM, DI, DI, DM, DM, frames);
}

// round 7
// speedup vs baseline: 1.2037x; 1.2037x over previous
#include <cuda_runtime.h>
#include <math.h>
#include <stdint.h>

// ---- problem dims ----
#define DM   512
#define DI   1024
#define DS   64
#define DTR  32
#define NB   2
#define LSEQ 1024
#define NTOK (NB*LSEQ)
#define XDBW (DTR + 2*DS)   // 160
#define SPLITK_WX 4

// ---- scratch ----
__device__ float g_xn[NTOK*DM];
__device__ float g_xz[(size_t)NTOK*2*DI];
__device__ float g_x[(size_t)NTOK*DI];
__device__ float g_xdb[(size_t)NTOK*XDBW];
__device__ float g_xdb_part[(size_t)SPLITK_WX*NTOK*XDBW];
__device__ float g_delta[(size_t)NTOK*DI];
__device__ float g_yv[(size_t)NTOK*DI];

// =====================================================================
// helpers
// =====================================================================
__device__ __forceinline__ void cp_async16(uint32_t saddr, const void* gaddr) {
    asm volatile("cp.async.cg.shared.global [%0], [%1], 16;\n" :: "r"(saddr), "l"(gaddr));
}
#define CP_COMMIT() asm volatile("cp.async.commit_group;\n" ::: "memory")
#define CP_WAIT0()  asm volatile("cp.async.wait_group 0;\n" ::: "memory")

// =====================================================================
// LayerNorm
// =====================================================================
__global__ void ln_kernel(const float* __restrict__ frames,
                          const float* __restrict__ gamma,
                          const float* __restrict__ beta,
                          float* __restrict__ xn) {
    int m = blockIdx.x;
    int tid = threadIdx.x;
    const float4* r = (const float4*)(frames + (size_t)m * DM);
    float4 v = r[tid];
    float s  = v.x + v.y + v.z + v.w;
    float sq = v.x*v.x + v.y*v.y + v.z*v.z + v.w*v.w;
    #pragma unroll
    for (int o = 16; o; o >>= 1) {
        s  += __shfl_xor_sync(~0u, s,  o);
        sq += __shfl_xor_sync(~0u, sq, o);
    }
    __shared__ float ss[4], ssq[4];
    int w = tid >> 5, lane = tid & 31;
    if (lane == 0) { ss[w] = s; ssq[w] = sq; }
    __syncthreads();
    s  = ss[0] + ss[1] + ss[2] + ss[3];
    sq = ssq[0] + ssq[1] + ssq[2] + ssq[3];
    float mean = s * (1.f / DM);
    float var  = sq * (1.f / DM) - mean * mean;
    float rstd = rsqrtf(var + 1e-5f);
    float4 g  = ((const float4*)gamma)[tid];
    float4 bt = ((const float4*)beta)[tid];
    float4 o;
    o.x = (v.x - mean) * rstd * g.x + bt.x;
    o.y = (v.y - mean) * rstd * g.y + bt.y;
    o.z = (v.z - mean) * rstd * g.z + bt.z;
    o.w = (v.w - mean) * rstd * g.w + bt.w;
    ((float4*)(xn + (size_t)m * DM))[tid] = o;
}

// =====================================================================
// TF32 tensor-core GEMM, cp.async double-buffered, BK=32. (R3 proven)
// =====================================================================
#define EPI_NONE     0
#define EPI_SOFTPLUS 1
#define EPI_RESID    2
#define EPI_PART     3

__device__ __forceinline__ void mma_tf32(float c[4], const uint32_t a[4], const uint32_t b[2]) {
    asm volatile(
        "mma.sync.aligned.m16n8k8.row.col.f32.tf32.tf32.f32 "
        "{%0,%1,%2,%3}, {%4,%5,%6,%7}, {%8,%9}, {%0,%1,%2,%3};"
        : "+f"(c[0]), "+f"(c[1]), "+f"(c[2]), "+f"(c[3])
        : "r"(a[0]), "r"(a[1]), "r"(a[2]), "r"(a[3]), "r"(b[0]), "r"(b[1]));
}

template<int BM, int BN, int EPI, int SPLITK>
__global__ void tgemm_kernel(const float* __restrict__ A,
                             const float* __restrict__ B,
                             float* __restrict__ C,
                             int M, int N, int K,
                             int lda, int ldb, int ldc,
                             const float* __restrict__ aux) {
    constexpr int BK = 32;
    constexpr int WM = BM / 32, WN = BN / 32;
    constexpr int THREADS = WM * WN * 32;
    constexpr int AST = BK + 4;
    constexpr int BST = BN + 8;
    constexpr int ABUF = BM * AST;
    constexpr int BBUF = BK * BST;

    extern __shared__ float sm[];
    float* Asm = sm;
    float* Bsm = sm + 2 * ABUF;
    uint32_t sa = (uint32_t)__cvta_generic_to_shared(Asm);
    uint32_t sb = (uint32_t)__cvta_generic_to_shared(Bsm);

    int tid = threadIdx.x, lane = tid & 31, wid = tid >> 5;
    int wm = wid % WM, wn = wid / WM;
    int m0 = blockIdx.y * BM, n0 = blockIdx.x * BN;
    int wrow = wm * 32, wcol = wn * 32;
    int g = lane >> 2, tg = lane & 3;

    int kbase = (SPLITK > 1) ? blockIdx.z * (K / SPLITK) : 0;
    int kcnt  = (K / SPLITK) / BK;

    float acc[2][4][4];
    #pragma unroll
    for (int a = 0; a < 2; a++)
        #pragma unroll
        for (int b = 0; b < 4; b++)
            #pragma unroll
            for (int c = 0; c < 4; c++) acc[a][b][c] = 0.f;

    auto loadA = [&](int kt, int buf) {
        const float* Ap = A + (size_t)m0 * lda + kbase + kt * BK;
        #pragma unroll
        for (int i = tid; i < BM * (BK / 4); i += THREADS) {
            int r = i / (BK / 4), c = (i % (BK / 4)) * 4;
            cp_async16(sa + (uint32_t)(buf * ABUF + r * AST + c) * 4,
                       Ap + (size_t)r * lda + c);
        }
    };
    auto loadB = [&](int kt, int buf) {
        const float* Bp = B + (size_t)(kbase + kt * BK) * ldb + n0;
        #pragma unroll
        for (int i = tid; i < BK * (BN / 4); i += THREADS) {
            int r = i / (BN / 4), c = (i % (BN / 4)) * 4;
            cp_async16(sb + (uint32_t)(buf * BBUF + r * BST + c) * 4,
                       Bp + (size_t)r * ldb + c);
        }
    };

    loadA(0, 0); loadB(0, 0); CP_COMMIT();

    for (int kt = 0; kt < kcnt; kt++) {
        CP_WAIT0();
        __syncthreads();
        if (kt + 1 < kcnt) {
            int nb = (kt + 1) & 1;
            loadA(kt + 1, nb); loadB(kt + 1, nb); CP_COMMIT();
        }
        int cb = kt & 1;
        const float* Ab = Asm + cb * ABUF;
        const float* Bb = Bsm + cb * BBUF;
        #pragma unroll
        for (int ks = 0; ks < 4; ks++) {
            int kb = ks * 8;
            uint32_t af[2][4], bf[4][2];
            #pragma unroll
            for (int mt = 0; mt < 2; mt++) {
                int r = wrow + mt * 16;
                af[mt][0] = __float_as_uint(Ab[(r + g)     * AST + kb + tg]);
                af[mt][1] = __float_as_uint(Ab[(r + 8 + g) * AST + kb + tg]);
                af[mt][2] = __float_as_uint(Ab[(r + g)     * AST + kb + 4 + tg]);
                af[mt][3] = __float_as_uint(Ab[(r + 8 + g) * AST + kb + 4 + tg]);
            }
            #pragma unroll
            for (int nt = 0; nt < 4; nt++) {
                int c = wcol + nt * 8 + g;
                bf[nt][0] = __float_as_uint(Bb[(kb + tg)     * BST + c]);
                bf[nt][1] = __float_as_uint(Bb[(kb + 4 + tg) * BST + c]);
            }
            #pragma unroll
            for (int mt = 0; mt < 2; mt++)
                #pragma unroll
                for (int nt = 0; nt < 4; nt++)
                    mma_tf32(acc[mt][nt], af[mt], bf[nt]);
        }
        __syncthreads();
    }

    float* Cw = C;
    if (EPI == EPI_PART) Cw = C + (size_t)blockIdx.z * M * ldc;

    #pragma unroll
    for (int mt = 0; mt < 2; mt++) {
        #pragma unroll
        for (int nt = 0; nt < 4; nt++) {
            int row0 = m0 + wrow + mt * 16 + g;
            int col  = n0 + wcol + nt * 8 + tg * 2;
            #pragma unroll
            for (int h = 0; h < 2; h++) {
                size_t row = row0 + h * 8;
                float v0 = acc[mt][nt][h * 2 + 0];
                float v1 = acc[mt][nt][h * 2 + 1];
                if (EPI == EPI_SOFTPLUS) {
                    v0 += aux[col];     v1 += aux[col + 1];
                    v0 = fmaxf(v0, 0.f) + log1pf(__expf(-fabsf(v0)));
                    v1 = fmaxf(v1, 0.f) + log1pf(__expf(-fabsf(v1)));
                }
                if (EPI == EPI_RESID) {
                    v0 += aux[row * ldc + col];
                    v1 += aux[row * ldc + col + 1];
                }
                *(float2*)(Cw + row * ldc + col) = make_float2(v0, v1);
            }
        }
    }
}

// =====================================================================
// reduce split-K partials
// =====================================================================
__global__ void reduce4_kernel(const float4* __restrict__ part,
                               float4* __restrict__ out, int n4) {
    int i = blockIdx.x * blockDim.x + threadIdx.x;
    if (i >= n4) return;
    float4 o = part[i];
    #pragma unroll
    for (int p = 1; p < SPLITK_WX; p++) {
        float4 a = part[i + (size_t)p * n4];
        o.x += a.x; o.y += a.y; o.z += a.z; o.w += a.w;
    }
    out[i] = o;
}

// =====================================================================
// Causal depthwise conv + bias + SiLU
// =====================================================================
__global__ void conv_silu_kernel(const float* __restrict__ xz,
                                 const float* __restrict__ cw,
                                 const float* __restrict__ cb,
                                 float* __restrict__ xo) {
    int idx = blockIdx.x * blockDim.x + threadIdx.x;
    if (idx >= NTOK * DI) return;
    int d = idx & (DI - 1);
    int token = idx >> 10;
    int t = token & (LSEQ - 1);
    float4 w = ((const float4*)cw)[d];
    const float* p = xz + (size_t)token * (2 * DI) + d;
    float acc = cb[d];
    if (t >= 3) acc += w.x * p[-3 * 2 * DI];
    if (t >= 2) acc += w.y * p[-2 * 2 * DI];
    if (t >= 1) acc += w.z * p[-1 * 2 * DI];
    acc += w.w * p[0];
    xo[idx] = acc / (1.f + __expf(-acc));
}

// =====================================================================
// Selective scan + fused gated epilogue (R3 shape: 8 warps, 1 ch/warp).
// Lane holds states 2l,2l+1 -> LDS.64 for B/C. a pre-scaled by log2e,
// exp2f. Output yv = (y + x*D)*silu(z) written directly.
// =====================================================================
#define SCAN_WARPS 8
#define TCH 64
#define LOG2E 1.4426950408889634f

__global__ void scan_kernel(const float* __restrict__ delta,
                            const float* __restrict__ xconv,
                            const float* __restrict__ xdb,
                            const float* __restrict__ xz,
                            const float* __restrict__ A_log,
                            const float* __restrict__ Dv,
                            float* __restrict__ yv) {
    int b  = blockIdx.y;
    int d0 = blockIdx.x * SCAN_WARPS;
    int tid = threadIdx.x;
    int w = tid >> 5, lane = tid & 31;
    int d = d0 + w;

    __shared__ float  Bs[TCH][DS];
    __shared__ float  Cs[TCH][DS];
    __shared__ float2 ds2[SCAN_WARPS][TCH];   // (delta, x)
    __shared__ float  zs[SCAN_WARPS][TCH];

    float a0 = -__expf(A_log[(size_t)d * DS + 2 * lane])     * LOG2E;
    float a1 = -__expf(A_log[(size_t)d * DS + 2 * lane + 1]) * LOG2E;
    float Dval = Dv[d];
    float h0 = 0.f, h1 = 0.f;

    for (int tc = 0; tc < LSEQ; tc += TCH) {
        __syncthreads();
        for (int i = tid; i < TCH * (DS / 4); i += SCAN_WARPS * 32) {
            int t  = i >> 4;
            int s4 = (i & 15) << 2;
            const float* p = xdb + (size_t)(b * LSEQ + tc + t) * XDBW;
            *(float4*)&Bs[t][s4] = *(const float4*)(p + DTR + s4);
            *(float4*)&Cs[t][s4] = *(const float4*)(p + DTR + DS + s4);
        }
        for (int i = tid; i < SCAN_WARPS * TCH; i += SCAN_WARPS * 32) {
            int j = i & (SCAN_WARPS - 1);
            int t = i >> 3;
            size_t tok = (size_t)(b * LSEQ + tc + t);
            ds2[j][t] = make_float2(delta[tok * DI + d0 + j],
                                    xconv[tok * DI + d0 + j]);
            zs[j][t] = xz[tok * (2 * DI) + DI + d0 + j];
        }
        __syncthreads();

        #pragma unroll 4
        for (int i = 0; i < TCH; i++) {
            float2 dtxt = ds2[w][i];
            float dt = dtxt.x, xt = dtxt.y;
            float dx = dt * xt;
            float2 bv = *(float2*)&Bs[i][2 * lane];
            float2 cv = *(float2*)&Cs[i][2 * lane];
            float dA0 = exp2f(dt * a0);
            float dA1 = exp2f(dt * a1);
            h0 = fmaf(h0, dA0, dx * bv.x);
            h1 = fmaf(h1, dA1, dx * bv.y);
            float p = fmaf(h0, cv.x, h1 * cv.y);
            p += __shfl_xor_sync(~0u, p, 16);
            p += __shfl_xor_sync(~0u, p, 8);
            p += __shfl_xor_sync(~0u, p, 4);
            p += __shfl_xor_sync(~0u, p, 2);
            p += __shfl_xor_sync(~0u, p, 1);
            if (lane == 0) {
                float z = zs[w][i];
                float sz = z / (1.f + __expf(-z));
                yv[(size_t)(b * LSEQ + tc + i) * DI + d] = fmaf(xt, Dval, p) * sz;
            }
        }
    }
}

// =====================================================================
// launch
// =====================================================================
extern "C" void kernel_launch(void* const* d_in, const int* in_sizes, int n_in,
                              void* d_out, int out_size) {
    const float* frames = (const float*)d_in[0];
    const float* gamma  = (const float*)d_in[1];
    const float* beta   = (const float*)d_in[2];
    const float* W_in   = (const float*)d_in[3];
    const float* conv_w = (const float*)d_in[4];
    const float* conv_b = (const float*)d_in[5];
    const float* W_x    = (const float*)d_in[6];
    const float* W_dt   = (const float*)d_in[7];
    const float* b_dt   = (const float*)d_in[8];
    const float* A_log  = (const float*)d_in[9];
    const float* Dv     = (const float*)d_in[10];
    const float* W_out  = (const float*)d_in[11];
    float* out = (float*)d_out;

    float *xn, *xz, *x, *xdb, *xdbp, *delta, *yv;
    cudaGetSymbolAddress((void**)&xn,    g_xn);
    cudaGetSymbolAddress((void**)&xz,    g_xz);
    cudaGetSymbolAddress((void**)&x,     g_x);
    cudaGetSymbolAddress((void**)&xdb,   g_xdb);
    cudaGetSymbolAddress((void**)&xdbp,  g_xdb_part);
    cudaGetSymbolAddress((void**)&delta, g_delta);
    cudaGetSymbolAddress((void**)&yv,    g_yv);

    constexpr int SM_IN  = (2*128*36 + 2*32*136) * 4;  // 71680 (BM128,BN128)
    constexpr int SM_WX  = (2*128*36 + 2*32*40)  * 4;  // 47104 (BM128,BN32)
    constexpr int SM_64  = (2*128*36 + 2*32*72)  * 4;  // 55296 (BM128,BN64)

    static bool attr_done = false;
    if (!attr_done) {
        cudaFuncSetAttribute((const void*)tgemm_kernel<128,128,EPI_NONE,1>,
                             cudaFuncAttributeMaxDynamicSharedMemorySize, SM_IN);
        cudaFuncSetAttribute((const void*)tgemm_kernel<128,32,EPI_PART,SPLITK_WX>,
                             cudaFuncAttributeMaxDynamicSharedMemorySize, SM_WX);
        cudaFuncSetAttribute((const void*)tgemm_kernel<128,64,EPI_SOFTPLUS,1>,
                             cudaFuncAttributeMaxDynamicSharedMemorySize, SM_64);
        cudaFuncSetAttribute((const void*)tgemm_kernel<128,64,EPI_RESID,1>,
                             cudaFuncAttributeMaxDynamicSharedMemorySize, SM_64);
        attr_done = true;
    }

    // 1. LayerNorm
    ln_kernel<<<NTOK, 128>>>(frames, gamma, beta, xn);

    // 2. in_proj: xz = xn @ W_in  (2048 x 2048 x 512)
    tgemm_kernel<128,128,EPI_NONE,1>
        <<<dim3(2*DI/128, NTOK/128), 512, SM_IN>>>(xn, W_in, xz,
            NTOK, 2*DI, DM, DM, 2*DI, 2*DI, nullptr);

    // 3. causal conv + silu
    conv_silu_kernel<<<(NTOK*DI)/256, 256>>>(xz, conv_w, conv_b, x);

    // 4. xdb = x @ W_x  (2048 x 160 x 1024), split-K=4
    tgemm_kernel<128,32,EPI_PART,SPLITK_WX>
        <<<dim3(XDBW/32, NTOK/128, SPLITK_WX), 128, SM_WX>>>(x, W_x, xdbp,
            NTOK, XDBW, DI, DI, XDBW, XDBW, nullptr);
    reduce4_kernel<<<(NTOK*XDBW/4 + 255)/256, 256>>>(
        (const float4*)xdbp, (float4*)xdb, NTOK*XDBW/4);

    // 5. delta = softplus(xdb[:, :32] @ W_dt + b_dt)
    tgemm_kernel<128,64,EPI_SOFTPLUS,1>
        <<<dim3(DI/64, NTOK/128), 256, SM_64>>>(xdb, W_dt, delta,
            NTOK, DI, DTR, XDBW, DI, DI, b_dt);

    // 6. selective scan + fused gated epilogue
    scan_kernel<<<dim3(DI/SCAN_WARPS, NB), SCAN_WARPS*32>>>(
        delta, x, xdb, xz, A_log, Dv, yv);

    // 7. out_proj + residual
    tgemm_kernel<128,64,EPI_RESID,1>
        <<<dim3(DM/64, NTOK/128), 256, SM_64>>>(yv, W_out, out,
            NTOK, DM, DI, DI, DM, DM, frames);
}

// round 8
// speedup vs baseline: 1.2708x; 1.0558x over previous
#include <cuda_runtime.h>
#include <cuda_bf16.h>
#include <math.h>
#include <stdint.h>

// ---- problem dims ----
#define DM   512
#define DI   1024
#define DS   64
#define DTR  32
#define NB   2
#define LSEQ 1024
#define NTOK (NB*LSEQ)
#define XDBW (DTR + 2*DS)   // 160
#define SPLITK_WX 4

// ---- scratch ----
__device__ __nv_bfloat16 g_xnb[NTOK*DM];
__device__ __nv_bfloat16 g_winb[(size_t)DM*2*DI];
__device__ __nv_bfloat16 g_woutb[(size_t)DI*DM];
__device__ __nv_bfloat16 g_yvb[(size_t)NTOK*DI];
__device__ float g_xz[(size_t)NTOK*2*DI];
__device__ float g_x[(size_t)NTOK*DI];
__device__ float g_xdb[(size_t)NTOK*XDBW];
__device__ float g_xdb_part[(size_t)SPLITK_WX*NTOK*XDBW];
__device__ float g_delta[(size_t)NTOK*DI];

// =====================================================================
// helpers
// =====================================================================
__device__ __forceinline__ void cp_async16(uint32_t saddr, const void* gaddr) {
    asm volatile("cp.async.cg.shared.global [%0], [%1], 16;\n" :: "r"(saddr), "l"(gaddr));
}
#define CP_COMMIT() asm volatile("cp.async.commit_group;\n" ::: "memory")
#define CP_WAIT0()  asm volatile("cp.async.wait_group 0;\n" ::: "memory")

__device__ __forceinline__ void ldsm_x4(uint32_t r[4], uint32_t saddr) {
    asm volatile("ldmatrix.sync.aligned.m8n8.x4.shared.b16 {%0,%1,%2,%3}, [%4];"
        : "=r"(r[0]), "=r"(r[1]), "=r"(r[2]), "=r"(r[3]) : "r"(saddr));
}
__device__ __forceinline__ void ldsm_x4_t(uint32_t r[4], uint32_t saddr) {
    asm volatile("ldmatrix.sync.aligned.m8n8.x4.trans.shared.b16 {%0,%1,%2,%3}, [%4];"
        : "=r"(r[0]), "=r"(r[1]), "=r"(r[2]), "=r"(r[3]) : "r"(saddr));
}
__device__ __forceinline__ void mma_bf16(float c[4], const uint32_t a[4], const uint32_t b[2]) {
    asm volatile(
        "mma.sync.aligned.m16n8k16.row.col.f32.bf16.bf16.f32 "
        "{%0,%1,%2,%3}, {%4,%5,%6,%7}, {%8,%9}, {%0,%1,%2,%3};"
        : "+f"(c[0]), "+f"(c[1]), "+f"(c[2]), "+f"(c[3])
        : "r"(a[0]), "r"(a[1]), "r"(a[2]), "r"(a[3]), "r"(b[0]), "r"(b[1]));
}
__device__ __forceinline__ void mma_tf32(float c[4], const uint32_t a[4], const uint32_t b[2]) {
    asm volatile(
        "mma.sync.aligned.m16n8k8.row.col.f32.tf32.tf32.f32 "
        "{%0,%1,%2,%3}, {%4,%5,%6,%7}, {%8,%9}, {%0,%1,%2,%3};"
        : "+f"(c[0]), "+f"(c[1]), "+f"(c[2]), "+f"(c[3])
        : "r"(a[0]), "r"(a[1]), "r"(a[2]), "r"(a[3]), "r"(b[0]), "r"(b[1]));
}

// =====================================================================
// fp32 -> bf16 convert (weights)
// =====================================================================
__global__ void f2bf_kernel(const float2* __restrict__ in,
                            __nv_bfloat162* __restrict__ out, int n2) {
    int i = blockIdx.x * blockDim.x + threadIdx.x;
    if (i < n2) out[i] = __float22bfloat162_rn(in[i]);
}

// =====================================================================
// LayerNorm -> bf16 output
// =====================================================================
__global__ void ln_kernel(const float* __restrict__ frames,
                          const float* __restrict__ gamma,
                          const float* __restrict__ beta,
                          __nv_bfloat16* __restrict__ xnb) {
    int m = blockIdx.x;
    int tid = threadIdx.x;
    const float4* r = (const float4*)(frames + (size_t)m * DM);
    float4 v = r[tid];
    float s  = v.x + v.y + v.z + v.w;
    float sq = v.x*v.x + v.y*v.y + v.z*v.z + v.w*v.w;
    #pragma unroll
    for (int o = 16; o; o >>= 1) {
        s  += __shfl_xor_sync(~0u, s,  o);
        sq += __shfl_xor_sync(~0u, sq, o);
    }
    __shared__ float ss[4], ssq[4];
    int w = tid >> 5, lane = tid & 31;
    if (lane == 0) { ss[w] = s; ssq[w] = sq; }
    __syncthreads();
    s  = ss[0] + ss[1] + ss[2] + ss[3];
    sq = ssq[0] + ssq[1] + ssq[2] + ssq[3];
    float mean = s * (1.f / DM);
    float var  = sq * (1.f / DM) - mean * mean;
    float rstd = rsqrtf(var + 1e-5f);
    float4 g  = ((const float4*)gamma)[tid];
    float4 bt = ((const float4*)beta)[tid];
    float ox = (v.x - mean) * rstd * g.x + bt.x;
    float oy = (v.y - mean) * rstd * g.y + bt.y;
    float oz = (v.z - mean) * rstd * g.z + bt.z;
    float ow = (v.w - mean) * rstd * g.w + bt.w;
    __nv_bfloat162* op = (__nv_bfloat162*)(xnb + (size_t)m * DM);
    op[2*tid]     = __float22bfloat162_rn(make_float2(ox, oy));
    op[2*tid + 1] = __float22bfloat162_rn(make_float2(oz, ow));
}

// =====================================================================
// BF16 tensor-core GEMM (m16n8k16 + ldmatrix), cp.async double-buffer.
// A: MxK row-major bf16, B: KxN row-major bf16, C: MxN fp32.
// =====================================================================
#define EPI_NONE     0
#define EPI_SOFTPLUS 1
#define EPI_RESID    2
#define EPI_PART     3

template<int BM, int BN, int EPI>
__global__ void bgemm_kernel(const __nv_bfloat16* __restrict__ A,
                             const __nv_bfloat16* __restrict__ B,
                             float* __restrict__ C,
                             int M, int N, int K,
                             int lda, int ldb, int ldc,
                             const float* __restrict__ aux) {
    constexpr int BK = 32;
    constexpr int WM = BM / 32, WN = BN / 32;
    constexpr int THREADS = WM * WN * 32;
    constexpr int AST = BK + 8;   // bf16 elems: 40 -> 80B rows, LDSM conflict-free
    constexpr int BST = BN + 8;
    constexpr int ABUF = BM * AST;
    constexpr int BBUF = BK * BST;

    extern __shared__ __nv_bfloat16 smb[];
    __nv_bfloat16* Asm = smb;
    __nv_bfloat16* Bsm = smb + 2 * ABUF;
    uint32_t sa = (uint32_t)__cvta_generic_to_shared(Asm);
    uint32_t sb = (uint32_t)__cvta_generic_to_shared(Bsm);

    int tid = threadIdx.x, lane = tid & 31, wid = tid >> 5;
    int wm = wid % WM, wn = wid / WM;
    int m0 = blockIdx.y * BM, n0 = blockIdx.x * BN;
    int wrow = wm * 32, wcol = wn * 32;
    int g = lane >> 2, tg = lane & 3;
    int lr = (lane & 7) + ((lane >> 3) & 1) * 8;   // ldmatrix row-in-16
    int lk = (lane >> 4) * 8;                      // ldmatrix 8-col group

    float acc[2][4][4];
    #pragma unroll
    for (int a = 0; a < 2; a++)
        #pragma unroll
        for (int b = 0; b < 4; b++)
            #pragma unroll
            for (int c = 0; c < 4; c++) acc[a][b][c] = 0.f;

    auto loadA = [&](int kt, int buf) {
        const __nv_bfloat16* Ap = A + (size_t)m0 * lda + kt * BK;
        #pragma unroll
        for (int i = tid; i < BM * (BK / 8); i += THREADS) {
            int r = i / (BK / 8), c = (i % (BK / 8)) * 8;
            cp_async16(sa + (uint32_t)(buf * ABUF + r * AST + c) * 2,
                       Ap + (size_t)r * lda + c);
        }
    };
    auto loadB = [&](int kt, int buf) {
        const __nv_bfloat16* Bp = B + (size_t)(kt * BK) * ldb + n0;
        #pragma unroll
        for (int i = tid; i < BK * (BN / 8); i += THREADS) {
            int r = i / (BN / 8), c = (i % (BN / 8)) * 8;
            cp_async16(sb + (uint32_t)(buf * BBUF + r * BST + c) * 2,
                       Bp + (size_t)r * ldb + c);
        }
    };

    int kcnt = K / BK;
    loadA(0, 0); loadB(0, 0); CP_COMMIT();

    for (int kt = 0; kt < kcnt; kt++) {
        CP_WAIT0();
        __syncthreads();
        if (kt + 1 < kcnt) {
            int nb = (kt + 1) & 1;
            loadA(kt + 1, nb); loadB(kt + 1, nb); CP_COMMIT();
        }
        int cb = kt & 1;
        #pragma unroll
        for (int ks = 0; ks < 2; ks++) {
            int kb = ks * 16;
            uint32_t af[2][4], bfr[2][4];
            #pragma unroll
            for (int mt = 0; mt < 2; mt++) {
                uint32_t ad = sa + (uint32_t)(cb * ABUF + (wrow + mt * 16 + lr) * AST + kb + lk) * 2;
                ldsm_x4(af[mt], ad);
            }
            #pragma unroll
            for (int bg = 0; bg < 2; bg++) {
                uint32_t bd = sb + (uint32_t)(cb * BBUF + (kb + lr) * BST + wcol + bg * 16 + lk) * 2;
                ldsm_x4_t(bfr[bg], bd);
            }
            #pragma unroll
            for (int mt = 0; mt < 2; mt++)
                #pragma unroll
                for (int nt = 0; nt < 4; nt++)
                    mma_bf16(acc[mt][nt], af[mt], &bfr[nt >> 1][(nt & 1) * 2]);
        }
        __syncthreads();
    }

    #pragma unroll
    for (int mt = 0; mt < 2; mt++) {
        #pragma unroll
        for (int nt = 0; nt < 4; nt++) {
            int row0 = m0 + wrow + mt * 16 + g;
            int col  = n0 + wcol + nt * 8 + tg * 2;
            #pragma unroll
            for (int h = 0; h < 2; h++) {
                size_t row = row0 + h * 8;
                float v0 = acc[mt][nt][h * 2 + 0];
                float v1 = acc[mt][nt][h * 2 + 1];
                if (EPI == EPI_RESID) {
                    v0 += aux[row * ldc + col];
                    v1 += aux[row * ldc + col + 1];
                }
                *(float2*)(C + row * ldc + col) = make_float2(v0, v1);
            }
        }
    }
}

// =====================================================================
// TF32 GEMM (for the delta path), cp.async double-buffered, BK=32.
// =====================================================================
template<int BM, int BN, int EPI, int SPLITK>
__global__ void tgemm_kernel(const float* __restrict__ A,
                             const float* __restrict__ B,
                             float* __restrict__ C,
                             int M, int N, int K,
                             int lda, int ldb, int ldc,
                             const float* __restrict__ aux) {
    constexpr int BK = 32;
    constexpr int WM = BM / 32, WN = BN / 32;
    constexpr int THREADS = WM * WN * 32;
    constexpr int AST = BK + 4;
    constexpr int BST = BN + 8;
    constexpr int ABUF = BM * AST;
    constexpr int BBUF = BK * BST;

    extern __shared__ float sm[];
    float* Asm = sm;
    float* Bsm = sm + 2 * ABUF;
    uint32_t sa = (uint32_t)__cvta_generic_to_shared(Asm);
    uint32_t sb = (uint32_t)__cvta_generic_to_shared(Bsm);

    int tid = threadIdx.x, lane = tid & 31, wid = tid >> 5;
    int wm = wid % WM, wn = wid / WM;
    int m0 = blockIdx.y * BM, n0 = blockIdx.x * BN;
    int wrow = wm * 32, wcol = wn * 32;
    int g = lane >> 2, tg = lane & 3;

    int kbase = (SPLITK > 1) ? blockIdx.z * (K / SPLITK) : 0;
    int kcnt  = (K / SPLITK) / BK;

    float acc[2][4][4];
    #pragma unroll
    for (int a = 0; a < 2; a++)
        #pragma unroll
        for (int b = 0; b < 4; b++)
            #pragma unroll
            for (int c = 0; c < 4; c++) acc[a][b][c] = 0.f;

    auto loadA = [&](int kt, int buf) {
        const float* Ap = A + (size_t)m0 * lda + kbase + kt * BK;
        #pragma unroll
        for (int i = tid; i < BM * (BK / 4); i += THREADS) {
            int r = i / (BK / 4), c = (i % (BK / 4)) * 4;
            cp_async16(sa + (uint32_t)(buf * ABUF + r * AST + c) * 4,
                       Ap + (size_t)r * lda + c);
        }
    };
    auto loadB = [&](int kt, int buf) {
        const float* Bp = B + (size_t)(kbase + kt * BK) * ldb + n0;
        #pragma unroll
        for (int i = tid; i < BK * (BN / 4); i += THREADS) {
            int r = i / (BN / 4), c = (i % (BN / 4)) * 4;
            cp_async16(sb + (uint32_t)(buf * BBUF + r * BST + c) * 4,
                       Bp + (size_t)r * ldb + c);
        }
    };

    loadA(0, 0); loadB(0, 0); CP_COMMIT();

    for (int kt = 0; kt < kcnt; kt++) {
        CP_WAIT0();
        __syncthreads();
        if (kt + 1 < kcnt) {
            int nb = (kt + 1) & 1;
            loadA(kt + 1, nb); loadB(kt + 1, nb); CP_COMMIT();
        }
        int cb = kt & 1;
        const float* Ab = Asm + cb * ABUF;
        const float* Bb = Bsm + cb * BBUF;
        #pragma unroll
        for (int ks = 0; ks < 4; ks++) {
            int kb = ks * 8;
            uint32_t af[2][4], bf[4][2];
            #pragma unroll
            for (int mt = 0; mt < 2; mt++) {
                int r = wrow + mt * 16;
                af[mt][0] = __float_as_uint(Ab[(r + g)     * AST + kb + tg]);
                af[mt][1] = __float_as_uint(Ab[(r + 8 + g) * AST + kb + tg]);
                af[mt][2] = __float_as_uint(Ab[(r + g)     * AST + kb + 4 + tg]);
                af[mt][3] = __float_as_uint(Ab[(r + 8 + g) * AST + kb + 4 + tg]);
            }
            #pragma unroll
            for (int nt = 0; nt < 4; nt++) {
                int c = wcol + nt * 8 + g;
                bf[nt][0] = __float_as_uint(Bb[(kb + tg)     * BST + c]);
                bf[nt][1] = __float_as_uint(Bb[(kb + 4 + tg) * BST + c]);
            }
            #pragma unroll
            for (int mt = 0; mt < 2; mt++)
                #pragma unroll
                for (int nt = 0; nt < 4; nt++)
                    mma_tf32(acc[mt][nt], af[mt], bf[nt]);
        }
        __syncthreads();
    }

    float* Cw = C;
    if (EPI == EPI_PART) Cw = C + (size_t)blockIdx.z * M * ldc;

    #pragma unroll
    for (int mt = 0; mt < 2; mt++) {
        #pragma unroll
        for (int nt = 0; nt < 4; nt++) {
            int row0 = m0 + wrow + mt * 16 + g;
            int col  = n0 + wcol + nt * 8 + tg * 2;
            #pragma unroll
            for (int h = 0; h < 2; h++) {
                size_t row = row0 + h * 8;
                float v0 = acc[mt][nt][h * 2 + 0];
                float v1 = acc[mt][nt][h * 2 + 1];
                if (EPI == EPI_SOFTPLUS) {
                    v0 += aux[col];     v1 += aux[col + 1];
                    v0 = fmaxf(v0, 0.f) + log1pf(__expf(-fabsf(v0)));
                    v1 = fmaxf(v1, 0.f) + log1pf(__expf(-fabsf(v1)));
                }
                *(float2*)(Cw + row * ldc + col) = make_float2(v0, v1);
            }
        }
    }
}

// =====================================================================
// reduce split-K partials
// =====================================================================
__global__ void reduce4_kernel(const float4* __restrict__ part,
                               float4* __restrict__ out, int n4) {
    int i = blockIdx.x * blockDim.x + threadIdx.x;
    if (i >= n4) return;
    float4 o = part[i];
    #pragma unroll
    for (int p = 1; p < SPLITK_WX; p++) {
        float4 a = part[i + (size_t)p * n4];
        o.x += a.x; o.y += a.y; o.z += a.z; o.w += a.w;
    }
    out[i] = o;
}

// =====================================================================
// Causal depthwise conv + bias + SiLU
// =====================================================================
__global__ void conv_silu_kernel(const float* __restrict__ xz,
                                 const float* __restrict__ cw,
                                 const float* __restrict__ cb,
                                 float* __restrict__ xo) {
    int idx = blockIdx.x * blockDim.x + threadIdx.x;
    if (idx >= NTOK * DI) return;
    int d = idx & (DI - 1);
    int token = idx >> 10;
    int t = token & (LSEQ - 1);
    float4 w = ((const float4*)cw)[d];
    const float* p = xz + (size_t)token * (2 * DI) + d;
    float acc = cb[d];
    if (t >= 3) acc += w.x * p[-3 * 2 * DI];
    if (t >= 2) acc += w.y * p[-2 * 2 * DI];
    if (t >= 1) acc += w.z * p[-1 * 2 * DI];
    acc += w.w * p[0];
    xo[idx] = acc / (1.f + __expf(-acc));
}

// =====================================================================
// Selective scan + fused gated epilogue -> bf16 yv
// =====================================================================
#define SCAN_WARPS 8
#define TCH 64
#define LOG2E 1.4426950408889634f

__global__ void scan_kernel(const float* __restrict__ delta,
                            const float* __restrict__ xconv,
                            const float* __restrict__ xdb,
                            const float* __restrict__ xz,
                            const float* __restrict__ A_log,
                            const float* __restrict__ Dv,
                            __nv_bfloat16* __restrict__ yvb) {
    int b  = blockIdx.y;
    int d0 = blockIdx.x * SCAN_WARPS;
    int tid = threadIdx.x;
    int w = tid >> 5, lane = tid & 31;
    int d = d0 + w;

    __shared__ float  Bs[TCH][DS];
    __shared__ float  Cs[TCH][DS];
    __shared__ float2 ds2[SCAN_WARPS][TCH];
    __shared__ float  zs[SCAN_WARPS][TCH];

    float a0 = -__expf(A_log[(size_t)d * DS + 2 * lane])     * LOG2E;
    float a1 = -__expf(A_log[(size_t)d * DS + 2 * lane + 1]) * LOG2E;
    float Dval = Dv[d];
    float h0 = 0.f, h1 = 0.f;

    for (int tc = 0; tc < LSEQ; tc += TCH) {
        __syncthreads();
        for (int i = tid; i < TCH * (DS / 4); i += SCAN_WARPS * 32) {
            int t  = i >> 4;
            int s4 = (i & 15) << 2;
            const float* p = xdb + (size_t)(b * LSEQ + tc + t) * XDBW;
            *(float4*)&Bs[t][s4] = *(const float4*)(p + DTR + s4);
            *(float4*)&Cs[t][s4] = *(const float4*)(p + DTR + DS + s4);
        }
        for (int i = tid; i < SCAN_WARPS * TCH; i += SCAN_WARPS * 32) {
            int j = i & (SCAN_WARPS - 1);
            int t = i >> 3;
            size_t tok = (size_t)(b * LSEQ + tc + t);
            ds2[j][t] = make_float2(delta[tok * DI + d0 + j],
                                    xconv[tok * DI + d0 + j]);
            zs[j][t] = xz[tok * (2 * DI) + DI + d0 + j];
        }
        __syncthreads();

        #pragma unroll 4
        for (int i = 0; i < TCH; i++) {
            float2 dtxt = ds2[w][i];
            float dt = dtxt.x, xt = dtxt.y;
            float dx = dt * xt;
            float2 bv = *(float2*)&Bs[i][2 * lane];
            float2 cv = *(float2*)&Cs[i][2 * lane];
            float dA0 = exp2f(dt * a0);
            float dA1 = exp2f(dt * a1);
            h0 = fmaf(h0, dA0, dx * bv.x);
            h1 = fmaf(h1, dA1, dx * bv.y);
            float p = fmaf(h0, cv.x, h1 * cv.y);
            p += __shfl_xor_sync(~0u, p, 16);
            p += __shfl_xor_sync(~0u, p, 8);
            p += __shfl_xor_sync(~0u, p, 4);
            p += __shfl_xor_sync(~0u, p, 2);
            p += __shfl_xor_sync(~0u, p, 1);
            if (lane == 0) {
                float z = zs[w][i];
                float sz = z / (1.f + __expf(-z));
                yvb[(size_t)(b * LSEQ + tc + i) * DI + d] =
                    __float2bfloat16(fmaf(xt, Dval, p) * sz);
            }
        }
    }
}

// =====================================================================
// launch
// =====================================================================
extern "C" void kernel_launch(void* const* d_in, const int* in_sizes, int n_in,
                              void* d_out, int out_size) {
    const float* frames = (const float*)d_in[0];
    const float* gamma  = (const float*)d_in[1];
    const float* beta   = (const float*)d_in[2];
    const float* W_in   = (const float*)d_in[3];
    const float* conv_w = (const float*)d_in[4];
    const float* conv_b = (const float*)d_in[5];
    const float* W_x    = (const float*)d_in[6];
    const float* W_dt   = (const float*)d_in[7];
    const float* b_dt   = (const float*)d_in[8];
    const float* A_log  = (const float*)d_in[9];
    const float* Dv     = (const float*)d_in[10];
    const float* W_out  = (const float*)d_in[11];
    float* out = (float*)d_out;

    __nv_bfloat16 *xnb, *winb, *woutb, *yvb;
    float *xz, *x, *xdb, *xdbp, *delta;
    cudaGetSymbolAddress((void**)&xnb,   g_xnb);
    cudaGetSymbolAddress((void**)&winb,  g_winb);
    cudaGetSymbolAddress((void**)&woutb, g_woutb);
    cudaGetSymbolAddress((void**)&yvb,   g_yvb);
    cudaGetSymbolAddress((void**)&xz,    g_xz);
    cudaGetSymbolAddress((void**)&x,     g_x);
    cudaGetSymbolAddress((void**)&xdb,   g_xdb);
    cudaGetSymbolAddress((void**)&xdbp,  g_xdb_part);
    cudaGetSymbolAddress((void**)&delta, g_delta);

    constexpr int SMB_IN  = (2*128*40 + 2*32*136) * 2;  // 37888 B
    constexpr int SMB_OUT = (2*128*40 + 2*32*72)  * 2;  // 29696 B
    constexpr int SM_WX   = (2*128*36 + 2*32*40)  * 4;  // 47104 B
    constexpr int SM_64   = (2*128*36 + 2*32*72)  * 4;  // 55296 B

    static bool attr_done = false;
    if (!attr_done) {
        cudaFuncSetAttribute((const void*)bgemm_kernel<128,128,EPI_NONE>,
                             cudaFuncAttributeMaxDynamicSharedMemorySize, SMB_IN);
        cudaFuncSetAttribute((const void*)bgemm_kernel<128,64,EPI_RESID>,
                             cudaFuncAttributeMaxDynamicSharedMemorySize, SMB_OUT);
        cudaFuncSetAttribute((const void*)tgemm_kernel<128,32,EPI_PART,SPLITK_WX>,
                             cudaFuncAttributeMaxDynamicSharedMemorySize, SM_WX);
        cudaFuncSetAttribute((const void*)tgemm_kernel<128,64,EPI_SOFTPLUS,1>,
                             cudaFuncAttributeMaxDynamicSharedMemorySize, SM_64);
        attr_done = true;
    }

    // 0. weight conversions (bf16)
    f2bf_kernel<<<(DM*2*DI/2 + 255)/256, 256>>>(
        (const float2*)W_in, (__nv_bfloat162*)winb, DM*2*DI/2);
    f2bf_kernel<<<(DI*DM/2 + 255)/256, 256>>>(
        (const float2*)W_out, (__nv_bfloat162*)woutb, DI*DM/2);

    // 1. LayerNorm -> bf16
    ln_kernel<<<NTOK, 128>>>(frames, gamma, beta, xnb);

    // 2. in_proj: xz = xn @ W_in  (2048 x 2048 x 512), bf16 MMA
    bgemm_kernel<128,128,EPI_NONE>
        <<<dim3(2*DI/128, NTOK/128), 512, SMB_IN>>>(xnb, winb, xz,
            NTOK, 2*DI, DM, DM, 2*DI, 2*DI, nullptr);

    // 3. causal conv + silu
    conv_silu_kernel<<<(NTOK*DI)/256, 256>>>(xz, conv_w, conv_b, x);

    // 4. xdb = x @ W_x  (2048 x 160 x 1024), tf32 split-K=4
    tgemm_kernel<128,32,EPI_PART,SPLITK_WX>
        <<<dim3(XDBW/32, NTOK/128, SPLITK_WX), 128, SM_WX>>>(x, W_x, xdbp,
            NTOK, XDBW, DI, DI, XDBW, XDBW, nullptr);
    reduce4_kernel<<<(NTOK*XDBW/4 + 255)/256, 256>>>(
        (const float4*)xdbp, (float4*)xdb, NTOK*XDBW/4);

    // 5. delta = softplus(xdb[:, :32] @ W_dt + b_dt), tf32
    tgemm_kernel<128,64,EPI_SOFTPLUS,1>
        <<<dim3(DI/64, NTOK/128), 256, SM_64>>>(xdb, W_dt, delta,
            NTOK, DI, DTR, XDBW, DI, DI, b_dt);

    // 6. selective scan + fused gated epilogue -> bf16 yv
    scan_kernel<<<dim3(DI/SCAN_WARPS, NB), SCAN_WARPS*32>>>(
        delta, x, xdb, xz, A_log, Dv, yvb);

    // 7. out_proj + residual: out = yv @ W_out + frames, bf16 MMA
    bgemm_kernel<128,64,EPI_RESID>
        <<<dim3(DM/64, NTOK/128), 256, SMB_OUT>>>(yvb, woutb, out,
            NTOK, DM, DI, DI, DM, DM, frames);
}

// round 9
// speedup vs baseline: 1.7246x; 1.3571x over previous
#include <cuda_runtime.h>
#include <cuda_bf16.h>
#include <math.h>
#include <stdint.h>

// ---- problem dims ----
#define DM   512
#define DI   1024
#define DS   64
#define DTR  32
#define NB   2
#define LSEQ 1024
#define NTOK (NB*LSEQ)
#define XDBW (DTR + 2*DS)   // 160
#define SPLITK_WX 4
#define G    16             // time chunks
#define TCH  (LSEQ/G)       // 64 steps per chunk

// ---- scratch ----
__device__ __nv_bfloat16 g_xnb[NTOK*DM];
__device__ __nv_bfloat16 g_winb[(size_t)DM*2*DI];
__device__ __nv_bfloat16 g_woutb[(size_t)DI*DM];
__device__ __nv_bfloat16 g_yvb[(size_t)NTOK*DI];
__device__ float g_xz[(size_t)NTOK*2*DI];
__device__ float g_x[(size_t)NTOK*DI];
__device__ float g_xdb[(size_t)NTOK*XDBW];
__device__ float g_xdb_part[(size_t)SPLITK_WX*NTOK*XDBW];
__device__ float g_delta[(size_t)NTOK*DI];
// two-level scan intermediates: [b][g][d][DS]
__device__ float g_P[(size_t)NB*G*DI*DS];
__device__ float g_q[(size_t)NB*G*DI*DS];
__device__ float g_hs[(size_t)NB*G*DI*DS];

// =====================================================================
// helpers
// =====================================================================
__device__ __forceinline__ void cp_async16(uint32_t saddr, const void* gaddr) {
    asm volatile("cp.async.cg.shared.global [%0], [%1], 16;\n" :: "r"(saddr), "l"(gaddr));
}
#define CP_COMMIT() asm volatile("cp.async.commit_group;\n" ::: "memory")
#define CP_WAIT0()  asm volatile("cp.async.wait_group 0;\n" ::: "memory")

__device__ __forceinline__ float ex2(float x) {   // guaranteed MUFU
    float r;
    asm("ex2.approx.ftz.f32 %0, %1;" : "=f"(r) : "f"(x));
    return r;
}

__device__ __forceinline__ void ldsm_x4(uint32_t r[4], uint32_t saddr) {
    asm volatile("ldmatrix.sync.aligned.m8n8.x4.shared.b16 {%0,%1,%2,%3}, [%4];"
        : "=r"(r[0]), "=r"(r[1]), "=r"(r[2]), "=r"(r[3]) : "r"(saddr));
}
__device__ __forceinline__ void ldsm_x4_t(uint32_t r[4], uint32_t saddr) {
    asm volatile("ldmatrix.sync.aligned.m8n8.x4.trans.shared.b16 {%0,%1,%2,%3}, [%4];"
        : "=r"(r[0]), "=r"(r[1]), "=r"(r[2]), "=r"(r[3]) : "r"(saddr));
}
__device__ __forceinline__ void mma_bf16(float c[4], const uint32_t a[4], const uint32_t b[2]) {
    asm volatile(
        "mma.sync.aligned.m16n8k16.row.col.f32.bf16.bf16.f32 "
        "{%0,%1,%2,%3}, {%4,%5,%6,%7}, {%8,%9}, {%0,%1,%2,%3};"
        : "+f"(c[0]), "+f"(c[1]), "+f"(c[2]), "+f"(c[3])
        : "r"(a[0]), "r"(a[1]), "r"(a[2]), "r"(a[3]), "r"(b[0]), "r"(b[1]));
}
__device__ __forceinline__ void mma_tf32(float c[4], const uint32_t a[4], const uint32_t b[2]) {
    asm volatile(
        "mma.sync.aligned.m16n8k8.row.col.f32.tf32.tf32.f32 "
        "{%0,%1,%2,%3}, {%4,%5,%6,%7}, {%8,%9}, {%0,%1,%2,%3};"
        : "+f"(c[0]), "+f"(c[1]), "+f"(c[2]), "+f"(c[3])
        : "r"(a[0]), "r"(a[1]), "r"(a[2]), "r"(a[3]), "r"(b[0]), "r"(b[1]));
}

// =====================================================================
// fp32 -> bf16 convert
// =====================================================================
__global__ void f2bf_kernel(const float2* __restrict__ in,
                            __nv_bfloat162* __restrict__ out, int n2) {
    int i = blockIdx.x * blockDim.x + threadIdx.x;
    if (i < n2) out[i] = __float22bfloat162_rn(in[i]);
}

// =====================================================================
// LayerNorm -> bf16
// =====================================================================
__global__ void ln_kernel(const float* __restrict__ frames,
                          const float* __restrict__ gamma,
                          const float* __restrict__ beta,
                          __nv_bfloat16* __restrict__ xnb) {
    int m = blockIdx.x;
    int tid = threadIdx.x;
    const float4* r = (const float4*)(frames + (size_t)m * DM);
    float4 v = r[tid];
    float s  = v.x + v.y + v.z + v.w;
    float sq = v.x*v.x + v.y*v.y + v.z*v.z + v.w*v.w;
    #pragma unroll
    for (int o = 16; o; o >>= 1) {
        s  += __shfl_xor_sync(~0u, s,  o);
        sq += __shfl_xor_sync(~0u, sq, o);
    }
    __shared__ float ss[4], ssq[4];
    int w = tid >> 5, lane = tid & 31;
    if (lane == 0) { ss[w] = s; ssq[w] = sq; }
    __syncthreads();
    s  = ss[0] + ss[1] + ss[2] + ss[3];
    sq = ssq[0] + ssq[1] + ssq[2] + ssq[3];
    float mean = s * (1.f / DM);
    float var  = sq * (1.f / DM) - mean * mean;
    float rstd = rsqrtf(var + 1e-5f);
    float4 g  = ((const float4*)gamma)[tid];
    float4 bt = ((const float4*)beta)[tid];
    float ox = (v.x - mean) * rstd * g.x + bt.x;
    float oy = (v.y - mean) * rstd * g.y + bt.y;
    float oz = (v.z - mean) * rstd * g.z + bt.z;
    float ow = (v.w - mean) * rstd * g.w + bt.w;
    __nv_bfloat162* op = (__nv_bfloat162*)(xnb + (size_t)m * DM);
    op[2*tid]     = __float22bfloat162_rn(make_float2(ox, oy));
    op[2*tid + 1] = __float22bfloat162_rn(make_float2(oz, ow));
}

// =====================================================================
// BF16 GEMM (m16n8k16 + ldmatrix), cp.async double-buffer
// =====================================================================
#define EPI_NONE     0
#define EPI_SOFTPLUS 1
#define EPI_RESID    2
#define EPI_PART     3

template<int BM, int BN, int EPI>
__global__ void bgemm_kernel(const __nv_bfloat16* __restrict__ A,
                             const __nv_bfloat16* __restrict__ B,
                             float* __restrict__ C,
                             int M, int N, int K,
                             int lda, int ldb, int ldc,
                             const float* __restrict__ aux) {
    constexpr int BK = 32;
    constexpr int WM = BM / 32, WN = BN / 32;
    constexpr int THREADS = WM * WN * 32;
    constexpr int AST = BK + 8;
    constexpr int BST = BN + 8;
    constexpr int ABUF = BM * AST;
    constexpr int BBUF = BK * BST;

    extern __shared__ __nv_bfloat16 smb[];
    __nv_bfloat16* Asm = smb;
    __nv_bfloat16* Bsm = smb + 2 * ABUF;
    uint32_t sa = (uint32_t)__cvta_generic_to_shared(Asm);
    uint32_t sb = (uint32_t)__cvta_generic_to_shared(Bsm);

    int tid = threadIdx.x, lane = tid & 31, wid = tid >> 5;
    int wm = wid % WM, wn = wid / WM;
    int m0 = blockIdx.y * BM, n0 = blockIdx.x * BN;
    int wrow = wm * 32, wcol = wn * 32;
    int g = lane >> 2, tg = lane & 3;
    int lr = (lane & 7) + ((lane >> 3) & 1) * 8;
    int lk = (lane >> 4) * 8;

    float acc[2][4][4];
    #pragma unroll
    for (int a = 0; a < 2; a++)
        #pragma unroll
        for (int b = 0; b < 4; b++)
            #pragma unroll
            for (int c = 0; c < 4; c++) acc[a][b][c] = 0.f;

    auto loadA = [&](int kt, int buf) {
        const __nv_bfloat16* Ap = A + (size_t)m0 * lda + kt * BK;
        #pragma unroll
        for (int i = tid; i < BM * (BK / 8); i += THREADS) {
            int r = i / (BK / 8), c = (i % (BK / 8)) * 8;
            cp_async16(sa + (uint32_t)(buf * ABUF + r * AST + c) * 2,
                       Ap + (size_t)r * lda + c);
        }
    };
    auto loadB = [&](int kt, int buf) {
        const __nv_bfloat16* Bp = B + (size_t)(kt * BK) * ldb + n0;
        #pragma unroll
        for (int i = tid; i < BK * (BN / 8); i += THREADS) {
            int r = i / (BN / 8), c = (i % (BN / 8)) * 8;
            cp_async16(sb + (uint32_t)(buf * BBUF + r * BST + c) * 2,
                       Bp + (size_t)r * ldb + c);
        }
    };

    int kcnt = K / BK;
    loadA(0, 0); loadB(0, 0); CP_COMMIT();

    for (int kt = 0; kt < kcnt; kt++) {
        CP_WAIT0();
        __syncthreads();
        if (kt + 1 < kcnt) {
            int nb = (kt + 1) & 1;
            loadA(kt + 1, nb); loadB(kt + 1, nb); CP_COMMIT();
        }
        int cb = kt & 1;
        #pragma unroll
        for (int ks = 0; ks < 2; ks++) {
            int kb = ks * 16;
            uint32_t af[2][4], bfr[2][4];
            #pragma unroll
            for (int mt = 0; mt < 2; mt++) {
                uint32_t ad = sa + (uint32_t)(cb * ABUF + (wrow + mt * 16 + lr) * AST + kb + lk) * 2;
                ldsm_x4(af[mt], ad);
            }
            #pragma unroll
            for (int bg = 0; bg < 2; bg++) {
                uint32_t bd = sb + (uint32_t)(cb * BBUF + (kb + lr) * BST + wcol + bg * 16 + lk) * 2;
                ldsm_x4_t(bfr[bg], bd);
            }
            #pragma unroll
            for (int mt = 0; mt < 2; mt++)
                #pragma unroll
                for (int nt = 0; nt < 4; nt++)
                    mma_bf16(acc[mt][nt], af[mt], &bfr[nt >> 1][(nt & 1) * 2]);
        }
        __syncthreads();
    }

    #pragma unroll
    for (int mt = 0; mt < 2; mt++) {
        #pragma unroll
        for (int nt = 0; nt < 4; nt++) {
            int row0 = m0 + wrow + mt * 16 + g;
            int col  = n0 + wcol + nt * 8 + tg * 2;
            #pragma unroll
            for (int h = 0; h < 2; h++) {
                size_t row = row0 + h * 8;
                float v0 = acc[mt][nt][h * 2 + 0];
                float v1 = acc[mt][nt][h * 2 + 1];
                if (EPI == EPI_RESID) {
                    v0 += aux[row * ldc + col];
                    v1 += aux[row * ldc + col + 1];
                }
                *(float2*)(C + row * ldc + col) = make_float2(v0, v1);
            }
        }
    }
}

// =====================================================================
// TF32 GEMM (delta path)
// =====================================================================
template<int BM, int BN, int EPI, int SPLITK>
__global__ void tgemm_kernel(const float* __restrict__ A,
                             const float* __restrict__ B,
                             float* __restrict__ C,
                             int M, int N, int K,
                             int lda, int ldb, int ldc,
                             const float* __restrict__ aux) {
    constexpr int BK = 32;
    constexpr int WM = BM / 32, WN = BN / 32;
    constexpr int THREADS = WM * WN * 32;
    constexpr int AST = BK + 4;
    constexpr int BST = BN + 8;
    constexpr int ABUF = BM * AST;
    constexpr int BBUF = BK * BST;

    extern __shared__ float sm[];
    float* Asm = sm;
    float* Bsm = sm + 2 * ABUF;
    uint32_t sa = (uint32_t)__cvta_generic_to_shared(Asm);
    uint32_t sb = (uint32_t)__cvta_generic_to_shared(Bsm);

    int tid = threadIdx.x, lane = tid & 31, wid = tid >> 5;
    int wm = wid % WM, wn = wid / WM;
    int m0 = blockIdx.y * BM, n0 = blockIdx.x * BN;
    int wrow = wm * 32, wcol = wn * 32;
    int g = lane >> 2, tg = lane & 3;

    int kbase = (SPLITK > 1) ? blockIdx.z * (K / SPLITK) : 0;
    int kcnt  = (K / SPLITK) / BK;

    float acc[2][4][4];
    #pragma unroll
    for (int a = 0; a < 2; a++)
        #pragma unroll
        for (int b = 0; b < 4; b++)
            #pragma unroll
            for (int c = 0; c < 4; c++) acc[a][b][c] = 0.f;

    auto loadA = [&](int kt, int buf) {
        const float* Ap = A + (size_t)m0 * lda + kbase + kt * BK;
        #pragma unroll
        for (int i = tid; i < BM * (BK / 4); i += THREADS) {
            int r = i / (BK / 4), c = (i % (BK / 4)) * 4;
            cp_async16(sa + (uint32_t)(buf * ABUF + r * AST + c) * 4,
                       Ap + (size_t)r * lda + c);
        }
    };
    auto loadB = [&](int kt, int buf) {
        const float* Bp = B + (size_t)(kbase + kt * BK) * ldb + n0;
        #pragma unroll
        for (int i = tid; i < BK * (BN / 4); i += THREADS) {
            int r = i / (BN / 4), c = (i % (BN / 4)) * 4;
            cp_async16(sb + (uint32_t)(buf * BBUF + r * BST + c) * 4,
                       Bp + (size_t)r * ldb + c);
        }
    };

    loadA(0, 0); loadB(0, 0); CP_COMMIT();

    for (int kt = 0; kt < kcnt; kt++) {
        CP_WAIT0();
        __syncthreads();
        if (kt + 1 < kcnt) {
            int nb = (kt + 1) & 1;
            loadA(kt + 1, nb); loadB(kt + 1, nb); CP_COMMIT();
        }
        int cb = kt & 1;
        const float* Ab = Asm + cb * ABUF;
        const float* Bb = Bsm + cb * BBUF;
        #pragma unroll
        for (int ks = 0; ks < 4; ks++) {
            int kb = ks * 8;
            uint32_t af[2][4], bf[4][2];
            #pragma unroll
            for (int mt = 0; mt < 2; mt++) {
                int r = wrow + mt * 16;
                af[mt][0] = __float_as_uint(Ab[(r + g)     * AST + kb + tg]);
                af[mt][1] = __float_as_uint(Ab[(r + 8 + g) * AST + kb + tg]);
                af[mt][2] = __float_as_uint(Ab[(r + g)     * AST + kb + 4 + tg]);
                af[mt][3] = __float_as_uint(Ab[(r + 8 + g) * AST + kb + 4 + tg]);
            }
            #pragma unroll
            for (int nt = 0; nt < 4; nt++) {
                int c = wcol + nt * 8 + g;
                bf[nt][0] = __float_as_uint(Bb[(kb + tg)     * BST + c]);
                bf[nt][1] = __float_as_uint(Bb[(kb + 4 + tg) * BST + c]);
            }
            #pragma unroll
            for (int mt = 0; mt < 2; mt++)
                #pragma unroll
                for (int nt = 0; nt < 4; nt++)
                    mma_tf32(acc[mt][nt], af[mt], bf[nt]);
        }
        __syncthreads();
    }

    float* Cw = C;
    if (EPI == EPI_PART) Cw = C + (size_t)blockIdx.z * M * ldc;

    #pragma unroll
    for (int mt = 0; mt < 2; mt++) {
        #pragma unroll
        for (int nt = 0; nt < 4; nt++) {
            int row0 = m0 + wrow + mt * 16 + g;
            int col  = n0 + wcol + nt * 8 + tg * 2;
            #pragma unroll
            for (int h = 0; h < 2; h++) {
                size_t row = row0 + h * 8;
                float v0 = acc[mt][nt][h * 2 + 0];
                float v1 = acc[mt][nt][h * 2 + 1];
                if (EPI == EPI_SOFTPLUS) {
                    v0 += aux[col];     v1 += aux[col + 1];
                    v0 = fmaxf(v0, 0.f) + log1pf(__expf(-fabsf(v0)));
                    v1 = fmaxf(v1, 0.f) + log1pf(__expf(-fabsf(v1)));
                }
                *(float2*)(Cw + row * ldc + col) = make_float2(v0, v1);
            }
        }
    }
}

// =====================================================================
// reduce split-K partials
// =====================================================================
__global__ void reduce4_kernel(const float4* __restrict__ part,
                               float4* __restrict__ out, int n4) {
    int i = blockIdx.x * blockDim.x + threadIdx.x;
    if (i >= n4) return;
    float4 o = part[i];
    #pragma unroll
    for (int p = 1; p < SPLITK_WX; p++) {
        float4 a = part[i + (size_t)p * n4];
        o.x += a.x; o.y += a.y; o.z += a.z; o.w += a.w;
    }
    out[i] = o;
}

// =====================================================================
// Causal depthwise conv + bias + SiLU
// =====================================================================
__global__ void conv_silu_kernel(const float* __restrict__ xz,
                                 const float* __restrict__ cw,
                                 const float* __restrict__ cb,
                                 float* __restrict__ xo) {
    int idx = blockIdx.x * blockDim.x + threadIdx.x;
    if (idx >= NTOK * DI) return;
    int d = idx & (DI - 1);
    int token = idx >> 10;
    int t = token & (LSEQ - 1);
    float4 w = ((const float4*)cw)[d];
    const float* p = xz + (size_t)token * (2 * DI) + d;
    float acc = cb[d];
    if (t >= 3) acc += w.x * p[-3 * 2 * DI];
    if (t >= 2) acc += w.y * p[-2 * 2 * DI];
    if (t >= 1) acc += w.z * p[-1 * 2 * DI];
    acc += w.w * p[0];
    xo[idx] = acc / (1.f + __expf(-acc));
}

// =====================================================================
// Two-level selective scan.
// Chunk recurrence: h_end = P (x) h_start + q  (diagonal per state).
// =====================================================================
#define SCAN_WARPS 8
#define LOG2E 1.4426950408889634f

// ---- Phase 1: per-(b,d,g) local scan from 0; emit P, q ----
__global__ void scan1_kernel(const float* __restrict__ delta,
                             const float* __restrict__ xconv,
                             const float* __restrict__ xdb,
                             const float* __restrict__ A_log,
                             float* __restrict__ Pout,
                             float* __restrict__ qout) {
    int b  = blockIdx.z;
    int g  = blockIdx.y;
    int d0 = blockIdx.x * SCAN_WARPS;
    int tid = threadIdx.x;
    int w = tid >> 5, lane = tid & 31;
    int d = d0 + w;
    int tc = g * TCH;

    __shared__ float  Bs[TCH][DS];
    __shared__ float2 ds2[SCAN_WARPS][TCH];

    float a0 = -__expf(A_log[(size_t)d * DS + 2 * lane])     * LOG2E;
    float a1 = -__expf(A_log[(size_t)d * DS + 2 * lane + 1]) * LOG2E;

    for (int i = tid; i < TCH * (DS / 4); i += SCAN_WARPS * 32) {
        int t  = i >> 4;
        int s4 = (i & 15) << 2;
        const float* p = xdb + (size_t)(b * LSEQ + tc + t) * XDBW;
        *(float4*)&Bs[t][s4] = *(const float4*)(p + DTR + s4);
    }
    for (int i = tid; i < SCAN_WARPS * TCH; i += SCAN_WARPS * 32) {
        int j = i & (SCAN_WARPS - 1);
        int t = i >> 3;
        size_t tok = (size_t)(b * LSEQ + tc + t);
        ds2[j][t] = make_float2(delta[tok * DI + d0 + j],
                                xconv[tok * DI + d0 + j]);
    }
    __syncthreads();

    float h0 = 0.f, h1 = 0.f, P0 = 1.f, P1 = 1.f;
    #pragma unroll 8
    for (int i = 0; i < TCH; i++) {
        float2 dtxt = ds2[w][i];
        float dt = dtxt.x;
        float dx = dt * dtxt.y;
        float2 bv = *(float2*)&Bs[i][2 * lane];
        float dA0 = ex2(dt * a0);
        float dA1 = ex2(dt * a1);
        h0 = fmaf(h0, dA0, dx * bv.x);
        h1 = fmaf(h1, dA1, dx * bv.y);
        P0 *= dA0;
        P1 *= dA1;
    }
    size_t base = (((size_t)b * G + g) * DI + d) * DS + 2 * lane;
    *(float2*)(Pout + base) = make_float2(P0, P1);
    *(float2*)(qout + base) = make_float2(h0, h1);
}

// ---- Phase 2: serial over chunks, per (b,d,state) ----
__global__ void scan2_kernel(const float* __restrict__ P,
                             const float* __restrict__ q,
                             float* __restrict__ hs) {
    int i = blockIdx.x * blockDim.x + threadIdx.x;   // over NB*DI*DS
    if (i >= NB * DI * DS) return;
    int b = i / (DI * DS);
    int rem = i - b * DI * DS;                       // d*DS + s
    float h = 0.f;
    #pragma unroll
    for (int g = 0; g < G; g++) {
        size_t idx = (((size_t)b * G + g) * DI * DS) + rem;
        hs[idx] = h;
        h = fmaf(P[idx], h, q[idx]);
    }
}

// ---- Phase 3: re-scan with h_start, full y + gated epilogue ----
__global__ void scan3_kernel(const float* __restrict__ delta,
                             const float* __restrict__ xconv,
                             const float* __restrict__ xdb,
                             const float* __restrict__ xz,
                             const float* __restrict__ A_log,
                             const float* __restrict__ Dv,
                             const float* __restrict__ hs,
                             __nv_bfloat16* __restrict__ yvb) {
    int b  = blockIdx.z;
    int g  = blockIdx.y;
    int d0 = blockIdx.x * SCAN_WARPS;
    int tid = threadIdx.x;
    int w = tid >> 5, lane = tid & 31;
    int d = d0 + w;
    int tc = g * TCH;

    __shared__ float  Bs[TCH][DS];
    __shared__ float  Cs[TCH][DS];
    __shared__ float2 ds2[SCAN_WARPS][TCH];
    __shared__ float  zs[SCAN_WARPS][TCH];

    float a0 = -__expf(A_log[(size_t)d * DS + 2 * lane])     * LOG2E;
    float a1 = -__expf(A_log[(size_t)d * DS + 2 * lane + 1]) * LOG2E;
    float Dval = Dv[d];

    for (int i = tid; i < TCH * (DS / 4); i += SCAN_WARPS * 32) {
        int t  = i >> 4;
        int s4 = (i & 15) << 2;
        const float* p = xdb + (size_t)(b * LSEQ + tc + t) * XDBW;
        *(float4*)&Bs[t][s4] = *(const float4*)(p + DTR + s4);
        *(float4*)&Cs[t][s4] = *(const float4*)(p + DTR + DS + s4);
    }
    for (int i = tid; i < SCAN_WARPS * TCH; i += SCAN_WARPS * 32) {
        int j = i & (SCAN_WARPS - 1);
        int t = i >> 3;
        size_t tok = (size_t)(b * LSEQ + tc + t);
        ds2[j][t] = make_float2(delta[tok * DI + d0 + j],
                                xconv[tok * DI + d0 + j]);
        zs[j][t] = xz[tok * (2 * DI) + DI + d0 + j];
    }
    __syncthreads();

    float2 h = *(const float2*)(hs + (((size_t)b * G + g) * DI + d) * DS + 2 * lane);
    float h0 = h.x, h1 = h.y;

    #pragma unroll 4
    for (int i = 0; i < TCH; i++) {
        float2 dtxt = ds2[w][i];
        float dt = dtxt.x, xt = dtxt.y;
        float dx = dt * xt;
        float2 bv = *(float2*)&Bs[i][2 * lane];
        float2 cv = *(float2*)&Cs[i][2 * lane];
        float dA0 = ex2(dt * a0);
        float dA1 = ex2(dt * a1);
        h0 = fmaf(h0, dA0, dx * bv.x);
        h1 = fmaf(h1, dA1, dx * bv.y);
        float p = fmaf(h0, cv.x, h1 * cv.y);
        p += __shfl_xor_sync(~0u, p, 16);
        p += __shfl_xor_sync(~0u, p, 8);
        p += __shfl_xor_sync(~0u, p, 4);
        p += __shfl_xor_sync(~0u, p, 2);
        p += __shfl_xor_sync(~0u, p, 1);
        if (lane == 0) {
            float z = zs[w][i];
            float sz = z / (1.f + __expf(-z));
            yvb[(size_t)(b * LSEQ + tc + i) * DI + d] =
                __float2bfloat16(fmaf(xt, Dval, p) * sz);
        }
    }
}

// =====================================================================
// launch
// =====================================================================
extern "C" void kernel_launch(void* const* d_in, const int* in_sizes, int n_in,
                              void* d_out, int out_size) {
    const float* frames = (const float*)d_in[0];
    const float* gamma  = (const float*)d_in[1];
    const float* beta   = (const float*)d_in[2];
    const float* W_in   = (const float*)d_in[3];
    const float* conv_w = (const float*)d_in[4];
    const float* conv_b = (const float*)d_in[5];
    const float* W_x    = (const float*)d_in[6];
    const float* W_dt   = (const float*)d_in[7];
    const float* b_dt   = (const float*)d_in[8];
    const float* A_log  = (const float*)d_in[9];
    const float* Dv     = (const float*)d_in[10];
    const float* W_out  = (const float*)d_in[11];
    float* out = (float*)d_out;

    __nv_bfloat16 *xnb, *winb, *woutb, *yvb;
    float *xz, *x, *xdb, *xdbp, *delta, *Pb, *qb, *hsb;
    cudaGetSymbolAddress((void**)&xnb,   g_xnb);
    cudaGetSymbolAddress((void**)&winb,  g_winb);
    cudaGetSymbolAddress((void**)&woutb, g_woutb);
    cudaGetSymbolAddress((void**)&yvb,   g_yvb);
    cudaGetSymbolAddress((void**)&xz,    g_xz);
    cudaGetSymbolAddress((void**)&x,     g_x);
    cudaGetSymbolAddress((void**)&xdb,   g_xdb);
    cudaGetSymbolAddress((void**)&xdbp,  g_xdb_part);
    cudaGetSymbolAddress((void**)&delta, g_delta);
    cudaGetSymbolAddress((void**)&Pb,    g_P);
    cudaGetSymbolAddress((void**)&qb,    g_q);
    cudaGetSymbolAddress((void**)&hsb,   g_hs);

    constexpr int SMB_IN  = (2*128*40 + 2*32*136) * 2;
    constexpr int SMB_OUT = (2*128*40 + 2*32*72)  * 2;
    constexpr int SM_WX   = (2*128*36 + 2*32*40)  * 4;
    constexpr int SM_64   = (2*128*36 + 2*32*72)  * 4;

    static bool attr_done = false;
    if (!attr_done) {
        cudaFuncSetAttribute((const void*)bgemm_kernel<128,128,EPI_NONE>,
                             cudaFuncAttributeMaxDynamicSharedMemorySize, SMB_IN);
        cudaFuncSetAttribute((const void*)bgemm_kernel<128,64,EPI_RESID>,
                             cudaFuncAttributeMaxDynamicSharedMemorySize, SMB_OUT);
        cudaFuncSetAttribute((const void*)tgemm_kernel<128,32,EPI_PART,SPLITK_WX>,
                             cudaFuncAttributeMaxDynamicSharedMemorySize, SM_WX);
        cudaFuncSetAttribute((const void*)tgemm_kernel<128,64,EPI_SOFTPLUS,1>,
                             cudaFuncAttributeMaxDynamicSharedMemorySize, SM_64);
        attr_done = true;
    }

    // 0. weight conversions
    f2bf_kernel<<<(DM*2*DI/2 + 255)/256, 256>>>(
        (const float2*)W_in, (__nv_bfloat162*)winb, DM*2*DI/2);
    f2bf_kernel<<<(DI*DM/2 + 255)/256, 256>>>(
        (const float2*)W_out, (__nv_bfloat162*)woutb, DI*DM/2);

    // 1. LayerNorm -> bf16
    ln_kernel<<<NTOK, 128>>>(frames, gamma, beta, xnb);

    // 2. in_proj (bf16)
    bgemm_kernel<128,128,EPI_NONE>
        <<<dim3(2*DI/128, NTOK/128), 512, SMB_IN>>>(xnb, winb, xz,
            NTOK, 2*DI, DM, DM, 2*DI, 2*DI, nullptr);

    // 3. conv + silu
    conv_silu_kernel<<<(NTOK*DI)/256, 256>>>(xz, conv_w, conv_b, x);

    // 4. xdb = x @ W_x (tf32, split-K4)
    tgemm_kernel<128,32,EPI_PART,SPLITK_WX>
        <<<dim3(XDBW/32, NTOK/128, SPLITK_WX), 128, SM_WX>>>(x, W_x, xdbp,
            NTOK, XDBW, DI, DI, XDBW, XDBW, nullptr);
    reduce4_kernel<<<(NTOK*XDBW/4 + 255)/256, 256>>>(
        (const float4*)xdbp, (float4*)xdb, NTOK*XDBW/4);

    // 5. delta (tf32 + softplus)
    tgemm_kernel<128,64,EPI_SOFTPLUS,1>
        <<<dim3(DI/64, NTOK/128), 256, SM_64>>>(xdb, W_dt, delta,
            NTOK, DI, DTR, XDBW, DI, DI, b_dt);

    // 6. two-level scan
    scan1_kernel<<<dim3(DI/SCAN_WARPS, G, NB), SCAN_WARPS*32>>>(
        delta, x, xdb, A_log, Pb, qb);
    scan2_kernel<<<(NB*DI*DS + 255)/256, 256>>>(Pb, qb, hsb);
    scan3_kernel<<<dim3(DI/SCAN_WARPS, G, NB), SCAN_WARPS*32>>>(
        delta, x, xdb, xz, A_log, Dv, hsb, yvb);

    // 7. out_proj + residual (bf16)
    bgemm_kernel<128,64,EPI_RESID>
        <<<dim3(DM/64, NTOK/128), 256, SMB_OUT>>>(yvb, woutb, out,
            NTOK, DM, DI, DI, DM, DM, frames);
}

// round 12
// speedup vs baseline: 1.8838x; 1.0923x over previous
#include <cuda_runtime.h>
#include <cuda_bf16.h>
#include <math.h>
#include <stdint.h>

// ---- problem dims ----
#define DM   512
#define DI   1024
#define DS   64
#define DTR  32
#define NB   2
#define LSEQ 1024
#define NTOK (NB*LSEQ)
#define XDBW (DTR + 2*DS)   // 160
#define SPLITK_WX 4
#define G    32             // time chunks
#define TCH  (LSEQ/G)       // 32 steps per chunk

// ---- scratch ----
__device__ __nv_bfloat16 g_xnb[NTOK*DM];
__device__ __nv_bfloat16 g_winb[(size_t)DM*2*DI];
__device__ __nv_bfloat16 g_woutb[(size_t)DI*DM];
__device__ __nv_bfloat16 g_yvb[(size_t)NTOK*DI];
__device__ float g_xz[(size_t)NTOK*2*DI];
__device__ float g_x[(size_t)NTOK*DI];
__device__ float2 g_fe[(size_t)NTOK*DI];       // (silu(z), x*D*silu(z))
__device__ float g_xdb[(size_t)NTOK*XDBW];
__device__ float g_xdb_part[(size_t)SPLITK_WX*NTOK*XDBW];
__device__ float g_delta[(size_t)NTOK*DI];
// two-level scan intermediates: [b][g][d][DS]
__device__ float g_P[(size_t)NB*G*DI*DS];
__device__ float g_q[(size_t)NB*G*DI*DS];
__device__ float g_hs[(size_t)NB*G*DI*DS];

// =====================================================================
// helpers
// =====================================================================
__device__ __forceinline__ void cp_async16(uint32_t saddr, const void* gaddr) {
    asm volatile("cp.async.cg.shared.global [%0], [%1], 16;\n" :: "r"(saddr), "l"(gaddr));
}
#define CP_COMMIT() asm volatile("cp.async.commit_group;\n" ::: "memory")
#define CP_WAIT0()  asm volatile("cp.async.wait_group 0;\n" ::: "memory")
#define CP_WAIT1()  asm volatile("cp.async.wait_group 1;\n" ::: "memory")

__device__ __forceinline__ float ex2(float x) {
    float r;
    asm("ex2.approx.ftz.f32 %0, %1;" : "=f"(r) : "f"(x));
    return r;
}

__device__ __forceinline__ void ldsm_x4(uint32_t r[4], uint32_t saddr) {
    asm volatile("ldmatrix.sync.aligned.m8n8.x4.shared.b16 {%0,%1,%2,%3}, [%4];"
        : "=r"(r[0]), "=r"(r[1]), "=r"(r[2]), "=r"(r[3]) : "r"(saddr));
}
__device__ __forceinline__ void ldsm_x4_t(uint32_t r[4], uint32_t saddr) {
    asm volatile("ldmatrix.sync.aligned.m8n8.x4.trans.shared.b16 {%0,%1,%2,%3}, [%4];"
        : "=r"(r[0]), "=r"(r[1]), "=r"(r[2]), "=r"(r[3]) : "r"(saddr));
}
__device__ __forceinline__ void mma_bf16(float c[4], const uint32_t a[4], const uint32_t b[2]) {
    asm volatile(
        "mma.sync.aligned.m16n8k16.row.col.f32.bf16.bf16.f32 "
        "{%0,%1,%2,%3}, {%4,%5,%6,%7}, {%8,%9}, {%0,%1,%2,%3};"
        : "+f"(c[0]), "+f"(c[1]), "+f"(c[2]), "+f"(c[3])
        : "r"(a[0]), "r"(a[1]), "r"(a[2]), "r"(a[3]), "r"(b[0]), "r"(b[1]));
}
__device__ __forceinline__ void mma_tf32(float c[4], const uint32_t a[4], const uint32_t b[2]) {
    asm volatile(
        "mma.sync.aligned.m16n8k8.row.col.f32.tf32.tf32.f32 "
        "{%0,%1,%2,%3}, {%4,%5,%6,%7}, {%8,%9}, {%0,%1,%2,%3};"
        : "+f"(c[0]), "+f"(c[1]), "+f"(c[2]), "+f"(c[3])
        : "r"(a[0]), "r"(a[1]), "r"(a[2]), "r"(a[3]), "r"(b[0]), "r"(b[1]));
}

// =====================================================================
// fp32 -> bf16 convert
// =====================================================================
__global__ void f2bf_kernel(const float2* __restrict__ in,
                            __nv_bfloat162* __restrict__ out, int n2) {
    int i = blockIdx.x * blockDim.x + threadIdx.x;
    if (i < n2) out[i] = __float22bfloat162_rn(in[i]);
}

// =====================================================================
// LayerNorm -> bf16
// =====================================================================
__global__ void ln_kernel(const float* __restrict__ frames,
                          const float* __restrict__ gamma,
                          const float* __restrict__ beta,
                          __nv_bfloat16* __restrict__ xnb) {
    int m = blockIdx.x;
    int tid = threadIdx.x;
    const float4* r = (const float4*)(frames + (size_t)m * DM);
    float4 v = r[tid];
    float s  = v.x + v.y + v.z + v.w;
    float sq = v.x*v.x + v.y*v.y + v.z*v.z + v.w*v.w;
    #pragma unroll
    for (int o = 16; o; o >>= 1) {
        s  += __shfl_xor_sync(~0u, s,  o);
        sq += __shfl_xor_sync(~0u, sq, o);
    }
    __shared__ float ss[4], ssq[4];
    int w = tid >> 5, lane = tid & 31;
    if (lane == 0) { ss[w] = s; ssq[w] = sq; }
    __syncthreads();
    s  = ss[0] + ss[1] + ss[2] + ss[3];
    sq = ssq[0] + ssq[1] + ssq[2] + ssq[3];
    float mean = s * (1.f / DM);
    float var  = sq * (1.f / DM) - mean * mean;
    float rstd = rsqrtf(var + 1e-5f);
    float4 g  = ((const float4*)gamma)[tid];
    float4 bt = ((const float4*)beta)[tid];
    float ox = (v.x - mean) * rstd * g.x + bt.x;
    float oy = (v.y - mean) * rstd * g.y + bt.y;
    float oz = (v.z - mean) * rstd * g.z + bt.z;
    float ow = (v.w - mean) * rstd * g.w + bt.w;
    __nv_bfloat162* op = (__nv_bfloat162*)(xnb + (size_t)m * DM);
    op[2*tid]     = __float22bfloat162_rn(make_float2(ox, oy));
    op[2*tid + 1] = __float22bfloat162_rn(make_float2(oz, ow));
}

// =====================================================================
// BF16 GEMM (m16n8k16 + ldmatrix), 3-stage cp.async pipeline
// =====================================================================
#define EPI_NONE     0
#define EPI_SOFTPLUS 1
#define EPI_RESID    2
#define EPI_PART     3

template<int BM, int BN, int EPI>
__global__ void bgemm_kernel(const __nv_bfloat16* __restrict__ A,
                             const __nv_bfloat16* __restrict__ B,
                             float* __restrict__ C,
                             int M, int N, int K,
                             int lda, int ldb, int ldc,
                             const float* __restrict__ aux) {
    constexpr int BK = 32;
    constexpr int WM = BM / 32, WN = BN / 32;
    constexpr int THREADS = WM * WN * 32;
    constexpr int AST = BK + 8;
    constexpr int BST = BN + 8;
    constexpr int ABUF = BM * AST;
    constexpr int BBUF = BK * BST;

    extern __shared__ __nv_bfloat16 smb[];
    __nv_bfloat16* Asm = smb;
    __nv_bfloat16* Bsm = smb + 3 * ABUF;
    uint32_t sa = (uint32_t)__cvta_generic_to_shared(Asm);
    uint32_t sb = (uint32_t)__cvta_generic_to_shared(Bsm);

    int tid = threadIdx.x, lane = tid & 31, wid = tid >> 5;
    int wm = wid % WM, wn = wid / WM;
    int m0 = blockIdx.y * BM, n0 = blockIdx.x * BN;
    int wrow = wm * 32, wcol = wn * 32;
    int g = lane >> 2, tg = lane & 3;
    int lr = (lane & 7) + ((lane >> 3) & 1) * 8;
    int lk = (lane >> 4) * 8;

    float acc[2][4][4];
    #pragma unroll
    for (int a = 0; a < 2; a++)
        #pragma unroll
        for (int b = 0; b < 4; b++)
            #pragma unroll
            for (int c = 0; c < 4; c++) acc[a][b][c] = 0.f;

    auto loadA = [&](int kt, int buf) {
        const __nv_bfloat16* Ap = A + (size_t)m0 * lda + kt * BK;
        #pragma unroll
        for (int i = tid; i < BM * (BK / 8); i += THREADS) {
            int r = i / (BK / 8), c = (i % (BK / 8)) * 8;
            cp_async16(sa + (uint32_t)(buf * ABUF + r * AST + c) * 2,
                       Ap + (size_t)r * lda + c);
        }
    };
    auto loadB = [&](int kt, int buf) {
        const __nv_bfloat16* Bp = B + (size_t)(kt * BK) * ldb + n0;
        #pragma unroll
        for (int i = tid; i < BK * (BN / 8); i += THREADS) {
            int r = i / (BN / 8), c = (i % (BN / 8)) * 8;
            cp_async16(sb + (uint32_t)(buf * BBUF + r * BST + c) * 2,
                       Bp + (size_t)r * ldb + c);
        }
    };

    int kcnt = K / BK;
    loadA(0, 0); loadB(0, 0); CP_COMMIT();
    loadA(1, 1); loadB(1, 1); CP_COMMIT();

    for (int kt = 0; kt < kcnt; kt++) {
        CP_WAIT1();
        __syncthreads();
        if (kt + 2 < kcnt) {
            int nb = (kt + 2) % 3;
            loadA(kt + 2, nb); loadB(kt + 2, nb); CP_COMMIT();
        }
        int cb = kt % 3;
        #pragma unroll
        for (int ks = 0; ks < 2; ks++) {
            int kb = ks * 16;
            uint32_t af[2][4], bfr[2][4];
            #pragma unroll
            for (int mt = 0; mt < 2; mt++) {
                uint32_t ad = sa + (uint32_t)(cb * ABUF + (wrow + mt * 16 + lr) * AST + kb + lk) * 2;
                ldsm_x4(af[mt], ad);
            }
            #pragma unroll
            for (int bg = 0; bg < 2; bg++) {
                uint32_t bd = sb + (uint32_t)(cb * BBUF + (kb + lr) * BST + wcol + bg * 16 + lk) * 2;
                ldsm_x4_t(bfr[bg], bd);
            }
            #pragma unroll
            for (int mt = 0; mt < 2; mt++)
                #pragma unroll
                for (int nt = 0; nt < 4; nt++)
                    mma_bf16(acc[mt][nt], af[mt], &bfr[nt >> 1][(nt & 1) * 2]);
        }
        __syncthreads();
    }

    #pragma unroll
    for (int mt = 0; mt < 2; mt++) {
        #pragma unroll
        for (int nt = 0; nt < 4; nt++) {
            int row0 = m0 + wrow + mt * 16 + g;
            int col  = n0 + wcol + nt * 8 + tg * 2;
            #pragma unroll
            for (int h = 0; h < 2; h++) {
                size_t row = row0 + h * 8;
                float v0 = acc[mt][nt][h * 2 + 0];
                float v1 = acc[mt][nt][h * 2 + 1];
                if (EPI == EPI_RESID) {
                    v0 += aux[row * ldc + col];
                    v1 += aux[row * ldc + col + 1];
                }
                *(float2*)(C + row * ldc + col) = make_float2(v0, v1);
            }
        }
    }
}

// =====================================================================
// TF32 GEMM (delta path), 2-stage (unchanged, proven)
// =====================================================================
template<int BM, int BN, int EPI, int SPLITK>
__global__ void tgemm_kernel(const float* __restrict__ A,
                             const float* __restrict__ B,
                             float* __restrict__ C,
                             int M, int N, int K,
                             int lda, int ldb, int ldc,
                             const float* __restrict__ aux) {
    constexpr int BK = 32;
    constexpr int WM = BM / 32, WN = BN / 32;
    constexpr int THREADS = WM * WN * 32;
    constexpr int AST = BK + 4;
    constexpr int BST = BN + 8;
    constexpr int ABUF = BM * AST;
    constexpr int BBUF = BK * BST;

    extern __shared__ float sm[];
    float* Asm = sm;
    float* Bsm = sm + 2 * ABUF;
    uint32_t sa = (uint32_t)__cvta_generic_to_shared(Asm);
    uint32_t sb = (uint32_t)__cvta_generic_to_shared(Bsm);

    int tid = threadIdx.x, lane = tid & 31, wid = tid >> 5;
    int wm = wid % WM, wn = wid / WM;
    int m0 = blockIdx.y * BM, n0 = blockIdx.x * BN;
    int wrow = wm * 32, wcol = wn * 32;
    int g = lane >> 2, tg = lane & 3;

    int kbase = (SPLITK > 1) ? blockIdx.z * (K / SPLITK) : 0;
    int kcnt  = (K / SPLITK) / BK;

    float acc[2][4][4];
    #pragma unroll
    for (int a = 0; a < 2; a++)
        #pragma unroll
        for (int b = 0; b < 4; b++)
            #pragma unroll
            for (int c = 0; c < 4; c++) acc[a][b][c] = 0.f;

    auto loadA = [&](int kt, int buf) {
        const float* Ap = A + (size_t)m0 * lda + kbase + kt * BK;
        #pragma unroll
        for (int i = tid; i < BM * (BK / 4); i += THREADS) {
            int r = i / (BK / 4), c = (i % (BK / 4)) * 4;
            cp_async16(sa + (uint32_t)(buf * ABUF + r * AST + c) * 4,
                       Ap + (size_t)r * lda + c);
        }
    };
    auto loadB = [&](int kt, int buf) {
        const float* Bp = B + (size_t)(kbase + kt * BK) * ldb + n0;
        #pragma unroll
        for (int i = tid; i < BK * (BN / 4); i += THREADS) {
            int r = i / (BN / 4), c = (i % (BN / 4)) * 4;
            cp_async16(sb + (uint32_t)(buf * BBUF + r * BST + c) * 4,
                       Bp + (size_t)r * ldb + c);
        }
    };

    loadA(0, 0); loadB(0, 0); CP_COMMIT();

    for (int kt = 0; kt < kcnt; kt++) {
        CP_WAIT0();
        __syncthreads();
        if (kt + 1 < kcnt) {
            int nb = (kt + 1) & 1;
            loadA(kt + 1, nb); loadB(kt + 1, nb); CP_COMMIT();
        }
        int cb = kt & 1;
        const float* Ab = Asm + cb * ABUF;
        const float* Bb = Bsm + cb * BBUF;
        #pragma unroll
        for (int ks = 0; ks < 4; ks++) {
            int kb = ks * 8;
            uint32_t af[2][4], bf[4][2];
            #pragma unroll
            for (int mt = 0; mt < 2; mt++) {
                int r = wrow + mt * 16;
                af[mt][0] = __float_as_uint(Ab[(r + g)     * AST + kb + tg]);
                af[mt][1] = __float_as_uint(Ab[(r + 8 + g) * AST + kb + tg]);
                af[mt][2] = __float_as_uint(Ab[(r + g)     * AST + kb + 4 + tg]);
                af[mt][3] = __float_as_uint(Ab[(r + 8 + g) * AST + kb + 4 + tg]);
            }
            #pragma unroll
            for (int nt = 0; nt < 4; nt++) {
                int c = wcol + nt * 8 + g;
                bf[nt][0] = __float_as_uint(Bb[(kb + tg)     * BST + c]);
                bf[nt][1] = __float_as_uint(Bb[(kb + 4 + tg) * BST + c]);
            }
            #pragma unroll
            for (int mt = 0; mt < 2; mt++)
                #pragma unroll
                for (int nt = 0; nt < 4; nt++)
                    mma_tf32(acc[mt][nt], af[mt], bf[nt]);
        }
        __syncthreads();
    }

    float* Cw = C;
    if (EPI == EPI_PART) Cw = C + (size_t)blockIdx.z * M * ldc;

    #pragma unroll
    for (int mt = 0; mt < 2; mt++) {
        #pragma unroll
        for (int nt = 0; nt < 4; nt++) {
            int row0 = m0 + wrow + mt * 16 + g;
            int col  = n0 + wcol + nt * 8 + tg * 2;
            #pragma unroll
            for (int h = 0; h < 2; h++) {
                size_t row = row0 + h * 8;
                float v0 = acc[mt][nt][h * 2 + 0];
                float v1 = acc[mt][nt][h * 2 + 1];
                if (EPI == EPI_SOFTPLUS) {
                    v0 += aux[col];     v1 += aux[col + 1];
                    v0 = fmaxf(v0, 0.f) + log1pf(__expf(-fabsf(v0)));
                    v1 = fmaxf(v1, 0.f) + log1pf(__expf(-fabsf(v1)));
                }
                *(float2*)(Cw + row * ldc + col) = make_float2(v0, v1);
            }
        }
    }
}

// =====================================================================
// reduce split-K partials
// =====================================================================
__global__ void reduce4_kernel(const float4* __restrict__ part,
                               float4* __restrict__ out, int n4) {
    int i = blockIdx.x * blockDim.x + threadIdx.x;
    if (i >= n4) return;
    float4 o = part[i];
    #pragma unroll
    for (int p = 1; p < SPLITK_WX; p++) {
        float4 a = part[i + (size_t)p * n4];
        o.x += a.x; o.y += a.y; o.z += a.z; o.w += a.w;
    }
    out[i] = o;
}

// =====================================================================
// Causal depthwise conv + bias + SiLU; also emits
// fe = (silu(z), x*D*silu(z)) for the scan epilogue.
// =====================================================================
__global__ void conv_fuse_kernel(const float* __restrict__ xz,
                                 const float* __restrict__ cw,
                                 const float* __restrict__ cb,
                                 const float* __restrict__ Dv,
                                 float* __restrict__ xo,
                                 float2* __restrict__ fe) {
    int idx = blockIdx.x * blockDim.x + threadIdx.x;
    if (idx >= NTOK * DI) return;
    int d = idx & (DI - 1);
    int token = idx >> 10;
    int t = token & (LSEQ - 1);
    float4 w = ((const float4*)cw)[d];
    const float* p = xz + (size_t)token * (2 * DI) + d;
    float acc = cb[d];
    if (t >= 3) acc += w.x * p[-3 * 2 * DI];
    if (t >= 2) acc += w.y * p[-2 * 2 * DI];
    if (t >= 1) acc += w.z * p[-1 * 2 * DI];
    acc += w.w * p[0];
    float xv = acc / (1.f + __expf(-acc));
    xo[idx] = xv;
    float z = xz[(size_t)token * (2 * DI) + DI + d];
    float sz = z / (1.f + __expf(-z));
    fe[idx] = make_float2(sz, xv * Dv[d] * sz);
}

// =====================================================================
// Two-level selective scan (G chunks of TCH).
// =====================================================================
#define SCAN_WARPS 8
#define LOG2E 1.4426950408889634f

// ---- Phase 1: local scan from 0; emit P = ex2(a*cumdelta), q ----
__global__ void scan1_kernel(const float* __restrict__ delta,
                             const float* __restrict__ xconv,
                             const float* __restrict__ xdb,
                             const float* __restrict__ A_log,
                             float* __restrict__ Pout,
                             float* __restrict__ qout) {
    int b  = blockIdx.z;
    int g  = blockIdx.y;
    int d0 = blockIdx.x * SCAN_WARPS;
    int tid = threadIdx.x;
    int w = tid >> 5, lane = tid & 31;
    int d = d0 + w;
    int tc = g * TCH;

    __shared__ float  Bs[TCH][DS];
    __shared__ float2 ds2[SCAN_WARPS][TCH];   // (dt, dt*x)

    float a0 = -__expf(A_log[(size_t)d * DS + 2 * lane])     * LOG2E;
    float a1 = -__expf(A_log[(size_t)d * DS + 2 * lane + 1]) * LOG2E;

    for (int i = tid; i < TCH * (DS / 4); i += SCAN_WARPS * 32) {
        int t  = i >> 4;
        int s4 = (i & 15) << 2;
        const float* p = xdb + (size_t)(b * LSEQ + tc + t) * XDBW;
        *(float4*)&Bs[t][s4] = *(const float4*)(p + DTR + s4);
    }
    for (int i = tid; i < SCAN_WARPS * TCH; i += SCAN_WARPS * 32) {
        int j = i & (SCAN_WARPS - 1);
        int t = i / SCAN_WARPS;
        size_t off = (size_t)(b * LSEQ + tc + t) * DI + d0 + j;
        float dt = delta[off];
        ds2[j][t] = make_float2(dt, dt * xconv[off]);
    }
    __syncthreads();

    float h0 = 0.f, h1 = 0.f, cd = 0.f;
    #pragma unroll 8
    for (int i = 0; i < TCH; i++) {
        float2 dtdx = ds2[w][i];
        float2 bv = *(float2*)&Bs[i][2 * lane];
        float dA0 = ex2(dtdx.x * a0);
        float dA1 = ex2(dtdx.x * a1);
        h0 = fmaf(h0, dA0, dtdx.y * bv.x);
        h1 = fmaf(h1, dA1, dtdx.y * bv.y);
        cd += dtdx.x;
    }
    size_t base = (((size_t)b * G + g) * DI + d) * DS + 2 * lane;
    *(float2*)(Pout + base) = make_float2(ex2(a0 * cd), ex2(a1 * cd));
    *(float2*)(qout + base) = make_float2(h0, h1);
}

// ---- Phase 2: serial over chunks, per (b,d,state) ----
__global__ void scan2_kernel(const float* __restrict__ P,
                             const float* __restrict__ q,
                             float* __restrict__ hs) {
    int i = blockIdx.x * blockDim.x + threadIdx.x;
    if (i >= NB * DI * DS) return;
    int b = i / (DI * DS);
    int rem = i - b * DI * DS;
    float h = 0.f;
    #pragma unroll
    for (int g = 0; g < G; g++) {
        size_t idx = (((size_t)b * G + g) * DI * DS) + rem;
        hs[idx] = h;
        h = fmaf(P[idx], h, q[idx]);
    }
}

// ---- Phase 3: re-scan with h_start; y, gated epilogue -> bf16 ----
__global__ void scan3_kernel(const float* __restrict__ delta,
                             const float* __restrict__ xconv,
                             const float* __restrict__ xdb,
                             const float2* __restrict__ fe,
                             const float* __restrict__ A_log,
                             const float* __restrict__ hs,
                             __nv_bfloat16* __restrict__ yvb) {
    int b  = blockIdx.z;
    int g  = blockIdx.y;
    int d0 = blockIdx.x * SCAN_WARPS;
    int tid = threadIdx.x;
    int w = tid >> 5, lane = tid & 31;
    int d = d0 + w;
    int tc = g * TCH;

    __shared__ float  Bs[TCH][DS];
    __shared__ float  Cs[TCH][DS];
    __shared__ float2 ds2[SCAN_WARPS][TCH];   // (dt, dt*x)
    __shared__ float2 fes[SCAN_WARPS][TCH];   // (f, e)

    float a0 = -__expf(A_log[(size_t)d * DS + 2 * lane])     * LOG2E;
    float a1 = -__expf(A_log[(size_t)d * DS + 2 * lane + 1]) * LOG2E;

    for (int i = tid; i < TCH * (DS / 4); i += SCAN_WARPS * 32) {
        int t  = i >> 4;
        int s4 = (i & 15) << 2;
        const float* p = xdb + (size_t)(b * LSEQ + tc + t) * XDBW;
        *(float4*)&Bs[t][s4] = *(const float4*)(p + DTR + s4);
        *(float4*)&Cs[t][s4] = *(const float4*)(p + DTR + DS + s4);
    }
    for (int i = tid; i < SCAN_WARPS * TCH; i += SCAN_WARPS * 32) {
        int j = i & (SCAN_WARPS - 1);
        int t = i / SCAN_WARPS;
        size_t off = (size_t)(b * LSEQ + tc + t) * DI + d0 + j;
        float dt = delta[off];
        ds2[j][t] = make_float2(dt, dt * xconv[off]);
        fes[j][t] = fe[off];
    }
    __syncthreads();

    float2 h = *(const float2*)(hs + (((size_t)b * G + g) * DI + d) * DS + 2 * lane);
    float h0 = h.x, h1 = h.y;

    #pragma unroll 4
    for (int i = 0; i < TCH; i++) {
        float2 dtdx = ds2[w][i];
        float2 bv = *(float2*)&Bs[i][2 * lane];
        float2 cv = *(float2*)&Cs[i][2 * lane];
        float dA0 = ex2(dtdx.x * a0);
        float dA1 = ex2(dtdx.x * a1);
        h0 = fmaf(h0, dA0, dtdx.y * bv.x);
        h1 = fmaf(h1, dA1, dtdx.y * bv.y);
        float p = fmaf(h0, cv.x, h1 * cv.y);
        p += __shfl_xor_sync(~0u, p, 16);
        p += __shfl_xor_sync(~0u, p, 8);
        p += __shfl_xor_sync(~0u, p, 4);
        p += __shfl_xor_sync(~0u, p, 2);
        p += __shfl_xor_sync(~0u, p, 1);
        if (lane == 0) {
            float2 fev = fes[w][i];
            yvb[(size_t)(b * LSEQ + tc + i) * DI + d] =
                __float2bfloat16(fmaf(p, fev.x, fev.y));
        }
    }
}

// =====================================================================
// launch
// =====================================================================
extern "C" void kernel_launch(void* const* d_in, const int* in_sizes, int n_in,
                              void* d_out, int out_size) {
    const float* frames = (const float*)d_in[0];
    const float* gamma  = (const float*)d_in[1];
    const float* beta   = (const float*)d_in[2];
    const float* W_in   = (const float*)d_in[3];
    const float* conv_w = (const float*)d_in[4];
    const float* conv_b = (const float*)d_in[5];
    const float* W_x    = (const float*)d_in[6];
    const float* W_dt   = (const float*)d_in[7];
    const float* b_dt   = (const float*)d_in[8];
    const float* A_log  = (const float*)d_in[9];
    const float* Dv     = (const float*)d_in[10];
    const float* W_out  = (const float*)d_in[11];
    float* out = (float*)d_out;

    __nv_bfloat16 *xnb, *winb, *woutb, *yvb;
    float *xz, *x, *xdb, *xdbp, *delta, *Pb, *qb, *hsb;
    float2 *feb;
    cudaGetSymbolAddress((void**)&xnb,   g_xnb);
    cudaGetSymbolAddress((void**)&winb,  g_winb);
    cudaGetSymbolAddress((void**)&woutb, g_woutb);
    cudaGetSymbolAddress((void**)&yvb,   g_yvb);
    cudaGetSymbolAddress((void**)&xz,    g_xz);
    cudaGetSymbolAddress((void**)&x,     g_x);
    cudaGetSymbolAddress((void**)&feb,   g_fe);
    cudaGetSymbolAddress((void**)&xdb,   g_xdb);
    cudaGetSymbolAddress((void**)&xdbp,  g_xdb_part);
    cudaGetSymbolAddress((void**)&delta, g_delta);
    cudaGetSymbolAddress((void**)&Pb,    g_P);
    cudaGetSymbolAddress((void**)&qb,    g_q);
    cudaGetSymbolAddress((void**)&hsb,   g_hs);

    constexpr int SMB_IN  = (3*128*40 + 3*32*136) * 2;  // 56448 B
    constexpr int SMB_OUT = (3*128*40 + 3*32*72)  * 2;  // 44544 B
    constexpr int SM_WX   = (2*128*36 + 2*32*40)  * 4;
    constexpr int SM_64   = (2*128*36 + 2*32*72)  * 4;

    static bool attr_done = false;
    if (!attr_done) {
        cudaFuncSetAttribute((const void*)bgemm_kernel<128,128,EPI_NONE>,
                             cudaFuncAttributeMaxDynamicSharedMemorySize, SMB_IN);
        cudaFuncSetAttribute((const void*)bgemm_kernel<128,64,EPI_RESID>,
                             cudaFuncAttributeMaxDynamicSharedMemorySize, SMB_OUT);
        cudaFuncSetAttribute((const void*)tgemm_kernel<128,32,EPI_PART,SPLITK_WX>,
                             cudaFuncAttributeMaxDynamicSharedMemorySize, SM_WX);
        cudaFuncSetAttribute((const void*)tgemm_kernel<128,64,EPI_SOFTPLUS,1>,
                             cudaFuncAttributeMaxDynamicSharedMemorySize, SM_64);
        attr_done = true;
    }

    // 0. weight conversions
    f2bf_kernel<<<(DM*2*DI/2 + 255)/256, 256>>>(
        (const float2*)W_in, (__nv_bfloat162*)winb, DM*2*DI/2);
    f2bf_kernel<<<(DI*DM/2 + 255)/256, 256>>>(
        (const float2*)W_out, (__nv_bfloat162*)woutb, DI*DM/2);

    // 1. LayerNorm -> bf16
    ln_kernel<<<NTOK, 128>>>(frames, gamma, beta, xnb);

    // 2. in_proj (bf16, 3-stage)
    bgemm_kernel<128,128,EPI_NONE>
        <<<dim3(2*DI/128, NTOK/128), 512, SMB_IN>>>(xnb, winb, xz,
            NTOK, 2*DI, DM, DM, 2*DI, 2*DI, nullptr);

    // 3. conv + silu + (silu(z), x*D*silu(z))
    conv_fuse_kernel<<<(NTOK*DI)/256, 256>>>(xz, conv_w, conv_b, Dv, x, feb);

    // 4. xdb = x @ W_x (tf32, split-K4)
    tgemm_kernel<128,32,EPI_PART,SPLITK_WX>
        <<<dim3(XDBW/32, NTOK/128, SPLITK_WX), 128, SM_WX>>>(x, W_x, xdbp,
            NTOK, XDBW, DI, DI, XDBW, XDBW, nullptr);
    reduce4_kernel<<<(NTOK*XDBW/4 + 255)/256, 256>>>(
        (const float4*)xdbp, (float4*)xdb, NTOK*XDBW/4);

    // 5. delta (tf32 + softplus)
    tgemm_kernel<128,64,EPI_SOFTPLUS,1>
        <<<dim3(DI/64, NTOK/128), 256, SM_64>>>(xdb, W_dt, delta,
            NTOK, DI, DTR, XDBW, DI, DI, b_dt);

    // 6. two-level scan
    scan1_kernel<<<dim3(DI/SCAN_WARPS, G, NB), SCAN_WARPS*32>>>(
        delta, x, xdb, A_log, Pb, qb);
    scan2_kernel<<<(NB*DI*DS + 255)/256, 256>>>(Pb, qb, hsb);
    scan3_kernel<<<dim3(DI/SCAN_WARPS, G, NB), SCAN_WARPS*32>>>(
        delta, x, xdb, feb, A_log, hsb, yvb);

    // 7. out_proj + residual (bf16, 3-stage)
    bgemm_kernel<128,64,EPI_RESID>
        <<<dim3(DM/64, NTOK/128), 256, SMB_OUT>>>(yvb, woutb, out,
            NTOK, DM, DI, DI, DM, DM, frames);
}